// round 12
// baseline (speedup 1.0000x reference)
#include <cuda_runtime.h>
#include <cuda_fp16.h>
#include <math.h>

#define D 4096
#define HID 4096
#define STEPS 16
#define FUS (5 * D)
#define SPLITK 256
#define ESPLIT 64
#define RES_SCALE 0.1f

// ---------------- scratch ----------------
#define OFF_FUSION   0
#define OFF_HBUF     (OFF_FUSION + FUS)
#define OFF_COND     (OFF_HBUF + HID)
#define OFF_STATE    (OFF_COND + D)
#define OFF_CONDC    (OFF_STATE + D)
#define OFF_EMBC     (OFF_CONDC + D)
#define OFF_H1       (OFF_EMBC + STEPS * D)
#define OFF_X        (OFF_H1 + D)
#define OFF_GI       (OFF_X + D)
#define OFF_GH       (OFF_GI + 3 * D)
#define OFF_PART     (OFF_GH + 3 * D)          // float[SPLITK*D]
#define OFF_PARTE    (OFF_PART + SPLITK * D)
#define OFF_DOTS     (OFF_PARTE + ESPLIT * STEPS * D)
#define SCRATCH_TOTAL (OFF_DOTS + 32)

__device__ float g_scratch[SCRATCH_TOTAL];

// fp16 copies of the recurring weights: [w_ih | w_hh | in_w1_state | in_w2]
#define H_WIH   ((size_t)0)
#define H_WHH   ((size_t)3 * D * D)
#define H_INW1S ((size_t)6 * D * D)
#define H_INW2  ((size_t)7 * D * D)
#define H_TOTAL ((size_t)8 * D * D)
__device__ __half g_half[H_TOTAL];

// ---------------- helpers ----------------
__device__ __forceinline__ float gelu_exact(float v) {
    return 0.5f * v * (1.0f + erff(v * 0.7071067811865476f));
}
__device__ __forceinline__ float sigmoidf(float v) {
    return 1.0f / (1.0f + expf(-v));
}

__device__ __forceinline__ unsigned long long ef_policy() {
    unsigned long long p;
    asm("createpolicy.fractional.L2::evict_first.b64 %0, 1.0;" : "=l"(p));
    return p;
}
__device__ __forceinline__ float4 ldg_ef_f4(const float4* p, unsigned long long pol) {
    float4 v;
    asm volatile("ld.global.L2::cache_hint.v4.f32 {%0,%1,%2,%3}, [%4], %5;"
                 : "=f"(v.x), "=f"(v.y), "=f"(v.z), "=f"(v.w) : "l"(p), "l"(pol));
    return v;
}

__device__ __forceinline__ uint2 pack_half4(float a, float b, float c, float d) {
    __half2 h0 = __floats2half2_rn(a, b);
    __half2 h1 = __floats2half2_rn(c, d);
    uint2 u;
    u.x = *reinterpret_cast<unsigned*>(&h0);
    u.y = *reinterpret_cast<unsigned*>(&h1);
    return u;
}

// warp-level fp16 row dot: acc = dot(W row, sx[0..1023] float4 staged vector)
__device__ __forceinline__ float rowdot_h(const uint4* Wr, const float4* sx, int lane) {
    float acc = 0.f;
    #pragma unroll
    for (int u = 0; u < 16; u++) {
        int i = lane + u * 32;
        uint4 w = __ldg(Wr + i);
        float4 x0 = sx[2 * i];
        float4 x1 = sx[2 * i + 1];
        float2 f0 = __half22float2(*reinterpret_cast<__half2*>(&w.x));
        float2 f1 = __half22float2(*reinterpret_cast<__half2*>(&w.y));
        float2 f2 = __half22float2(*reinterpret_cast<__half2*>(&w.z));
        float2 f3 = __half22float2(*reinterpret_cast<__half2*>(&w.w));
        acc += f0.x * x0.x + f0.y * x0.y + f1.x * x0.z + f1.y * x0.w;
        acc += f2.x * x1.x + f2.y * x1.y + f3.x * x1.z + f3.y * x1.w;
    }
    #pragma unroll
    for (int o = 16; o > 0; o >>= 1) acc += __shfl_down_sync(0xffffffffu, acc, o);
    return acc;
}

// ---------------- kernels ----------------

// fusion = [a, p, c, p-a, p*a]
__global__ void k_fusion(const float* __restrict__ a, const float* __restrict__ p,
                         const float* __restrict__ c) {
    int i = blockIdx.x * blockDim.x + threadIdx.x;
    float av = a[i], pv = p[i], cv = c[i];
    float* f = g_scratch + OFF_FUSION;
    f[i] = av; f[D + i] = pv; f[2 * D + i] = cv;
    f[3 * D + i] = pv - av; f[4 * D + i] = pv * av;
}

// fp32 col-major GEMV partial (one-time MLPs). x-slice staged in smem.
__global__ void k_gemv_col_part(const float* __restrict__ W, const float* __restrict__ x,
                                int K, float* __restrict__ part) {
    __shared__ float sx[128];
    unsigned long long pol = ef_policy();
    int tid = threadIdx.x;
    int j4 = (blockIdx.x * blockDim.x + tid) * 4;
    int ks = (int)(((long long)K * blockIdx.y) / gridDim.y);
    int ke = (int)(((long long)K * (blockIdx.y + 1)) / gridDim.y);
    int cnt = ke - ks;
    if (tid < cnt) sx[tid] = __ldg(&x[ks + tid]);
    __syncthreads();
    float4 acc = make_float4(0.f, 0.f, 0.f, 0.f);
    const float4* Wp = (const float4*)(W + (size_t)ks * D + j4);
    #pragma unroll 8
    for (int u = 0; u < cnt; u++) {
        float xv = sx[u];
        float4 w = ldg_ef_f4(Wp, pol);
        Wp += D / 4;
        acc.x = fmaf(xv, w.x, acc.x);
        acc.y = fmaf(xv, w.y, acc.y);
        acc.z = fmaf(xv, w.z, acc.z);
        acc.w = fmaf(xv, w.w, acc.w);
    }
    *(float4*)(part + (size_t)blockIdx.y * D + j4) = acc;
}

// Fused: fp32 GEMV partial + emit fp16 copy of W (step 0, in_w matrices; K == D)
__global__ void k_gemv_col_part_cvt(const float* __restrict__ W, const float* __restrict__ x,
                                    float* __restrict__ part, __half* __restrict__ W16) {
    __shared__ float sx[32];
    unsigned long long pol = ef_policy();
    int tid = threadIdx.x;
    int j4 = (blockIdx.x * blockDim.x + tid) * 4;
    int ks = blockIdx.y * (D / SPLITK);
    if (tid < D / SPLITK) sx[tid] = __ldg(&x[ks + tid]);
    __syncthreads();
    float4 acc = make_float4(0.f, 0.f, 0.f, 0.f);
    #pragma unroll
    for (int u = 0; u < D / SPLITK; u++) {
        int k = ks + u;
        float xv = sx[u];
        float4 w = ldg_ef_f4((const float4*)(W + (size_t)k * D + j4), pol);
        *(uint2*)(W16 + (size_t)k * D + j4) = pack_half4(w.x, w.y, w.z, w.w);
        acc.x = fmaf(xv, w.x, acc.x);
        acc.y = fmaf(xv, w.y, acc.y);
        acc.z = fmaf(xv, w.z, acc.z);
        acc.w = fmaf(xv, w.w, acc.w);
    }
    *(float4*)(part + (size_t)blockIdx.y * D + j4) = acc;
}

// fp16-weight col-major GEMV partial (R9-proven): uint2 loads, x-slice in registers.
// grid (D/(256*4)=4, SPLITK).
__global__ void k_gemv_col_part_h(const __half* __restrict__ W, const float* __restrict__ x,
                                  float* __restrict__ part) {
    int j4 = (blockIdx.x * blockDim.x + threadIdx.x) * 4;
    int ks = blockIdx.y * (D / SPLITK);
    float xs[D / SPLITK];
    #pragma unroll
    for (int u = 0; u < D / SPLITK; u++) xs[u] = __ldg(&x[ks + u]);
    float4 acc = make_float4(0.f, 0.f, 0.f, 0.f);
    #pragma unroll
    for (int u = 0; u < D / SPLITK; u++) {
        uint2 w = *(const uint2*)(W + (size_t)(ks + u) * D + j4);
        float2 f0 = __half22float2(*reinterpret_cast<__half2*>(&w.x));
        float2 f1 = __half22float2(*reinterpret_cast<__half2*>(&w.y));
        acc.x = fmaf(xs[u], f0.x, acc.x);
        acc.y = fmaf(xs[u], f0.y, acc.y);
        acc.z = fmaf(xs[u], f1.x, acc.z);
        acc.w = fmaf(xs[u], f1.y, acc.w);
    }
    *(float4*)(part + (size_t)blockIdx.y * D + j4) = acc;
}

// Combined step-head kernel: blocks [0, 3D/8) compute gh rows (W_hh @ state + b_hh);
// blocks [3D/8, 3D/8 + 1024) compute in_w1s col partials. Both depend only on state.
#define GH_BLOCKS ((3 * D) / 8)
__global__ void k_step_a(const __half* __restrict__ Whh, const float* __restrict__ state,
                         const float* __restrict__ bhh, float* __restrict__ gh,
                         const __half* __restrict__ Wcol, float* __restrict__ part) {
    __shared__ float4 sx[D / 4];
    int tid = threadIdx.x;
    if (blockIdx.x < GH_BLOCKS) {
        int warp = tid >> 5, lane = tid & 31;
        int row = blockIdx.x * 8 + warp;
        #pragma unroll
        for (int u = 0; u < 4; u++)
            sx[tid + u * 256] = __ldg(((const float4*)state) + tid + u * 256);
        __syncthreads();
        float acc = rowdot_h((const uint4*)(Whh + (size_t)row * D), sx, lane);
        if (lane == 0) gh[row] = acc + bhh[row];
    } else {
        int cb = blockIdx.x - GH_BLOCKS;       // 0..1023
        int jtile = cb & 3;
        int kslice = cb >> 2;                  // 0..255
        int j4 = (jtile * 256 + tid) * 4;
        int ks = kslice * (D / SPLITK);
        float xs[D / SPLITK];
        #pragma unroll
        for (int u = 0; u < D / SPLITK; u++) xs[u] = __ldg(&state[ks + u]);
        float4 acc = make_float4(0.f, 0.f, 0.f, 0.f);
        #pragma unroll
        for (int u = 0; u < D / SPLITK; u++) {
            uint2 w = *(const uint2*)(Wcol + (size_t)(ks + u) * D + j4);
            float2 f0 = __half22float2(*reinterpret_cast<__half2*>(&w.x));
            float2 f1 = __half22float2(*reinterpret_cast<__half2*>(&w.y));
            acc.x = fmaf(xs[u], f0.x, acc.x);
            acc.y = fmaf(xs[u], f0.y, acc.y);
            acc.z = fmaf(xs[u], f1.x, acc.z);
            acc.w = fmaf(xs[u], f1.y, acc.w);
        }
        *(float4*)(part + (size_t)kslice * D + j4) = acc;
    }
}

// Finish: sum SPLITK fp32 partials per j, apply epilogue.
__global__ void k_gemv_col_fin(const float* __restrict__ part,
                               const float* __restrict__ add0, const float* __restrict__ add1,
                               const float* __restrict__ bias, int act, float scale,
                               const float* __restrict__ residual, float* __restrict__ out) {
    __shared__ float sh[4][64];
    int jloc = threadIdx.x & 63;
    int tgrp = threadIdx.x >> 6;
    int j = blockIdx.x * 64 + jloc;
    float s = 0.f;
    #pragma unroll
    for (int t = tgrp; t < SPLITK; t += 4) s += part[(size_t)t * D + j];
    sh[tgrp][jloc] = s;
    __syncthreads();
    if (tgrp == 0) {
        s = sh[0][jloc] + sh[1][jloc] + sh[2][jloc] + sh[3][jloc];
        if (add0) s += add0[j];
        if (add1) s += add1[j];
        if (bias) s += bias[j];
        if (act) s = gelu_exact(s);
        if (residual) out[j] = residual[j] + scale * s;
        else out[j] = scale * s;
    }
}

// Step-embedding hoist (one-time, fp32)
__global__ void k_emb_part(const float* __restrict__ We, const float* __restrict__ emb,
                           float* __restrict__ part) {
    __shared__ float se[D / ESPLIT][STEPS];
    unsigned long long pol = ef_policy();
    int tid = threadIdx.x;
    int j = blockIdx.x * blockDim.x + tid;
    int ks = blockIdx.y * (D / ESPLIT);
    for (int i = tid; i < (D / ESPLIT) * STEPS; i += blockDim.x) {
        int kk = i / STEPS, tt = i % STEPS;
        se[kk][tt] = __ldg(&emb[tt * D + ks + kk]);
    }
    __syncthreads();
    float acc[STEPS];
    #pragma unroll
    for (int t = 0; t < STEPS; t++) acc[t] = 0.f;
    #pragma unroll 4
    for (int u = 0; u < D / ESPLIT; u++) {
        float w;
        asm volatile("ld.global.L2::cache_hint.f32 %0, [%1], %2;"
                     : "=f"(w) : "l"(&We[(size_t)(ks + u) * D + j]), "l"(pol));
        #pragma unroll
        for (int t = 0; t < STEPS; t++)
            acc[t] = fmaf(se[u][t], w, acc[t]);
    }
    #pragma unroll
    for (int t = 0; t < STEPS; t++)
        part[((size_t)blockIdx.y * STEPS + t) * D + j] = acc[t];
}

__global__ void k_emb_fin(const float* __restrict__ part, float* __restrict__ out) {
    int idx = blockIdx.x * blockDim.x + threadIdx.x;
    float s = 0.f;
    #pragma unroll
    for (int sp = 0; sp < ESPLIT; sp++) s += part[(size_t)sp * STEPS * D + idx];
    out[idx] = s;
}

// Single-matrix fp16 row GEMV (warp-per-row), vector staged in smem.
__global__ void k_gemv_row_h(const __half* __restrict__ W, const float* __restrict__ v,
                             const float* __restrict__ bias, float* __restrict__ out) {
    __shared__ float4 sx[D / 4];
    int tid = threadIdx.x;
    int warp = tid >> 5, lane = tid & 31;
    int row = blockIdx.x * 8 + warp;
    #pragma unroll
    for (int u = 0; u < 4; u++)
        sx[tid + u * 256] = __ldg(((const float4*)v) + tid + u * 256);
    __syncthreads();
    float acc = rowdot_h((const uint4*)(W + (size_t)row * D), sx, lane);
    if (lane == 0) out[row] = acc + bias[row];
}

// Step 0 variant: fp32 weights for both gate matrices, emits fp16 copies.
__global__ void k_gemv_row2_cvt(const float* __restrict__ Wih, const float* __restrict__ x,
                                const float* __restrict__ bih, float* __restrict__ gi,
                                const float* __restrict__ Whh, const float* __restrict__ st,
                                const float* __restrict__ bhh, float* __restrict__ gh,
                                __half* __restrict__ Wih16, __half* __restrict__ Whh16) {
    __shared__ float4 sx[D / 4];
    unsigned long long pol = ef_policy();
    int tid = threadIdx.x;
    int warp = tid >> 5, lane = tid & 31;
    int grow = blockIdx.x * 8 + warp;
    int second = grow >= 3 * D;
    int row = second ? grow - 3 * D : grow;
    const float* W   = second ? Whh : Wih;
    const float* v   = second ? st  : x;
    const float* bb  = second ? bhh : bih;
    float* outp      = second ? gh  : gi;
    __half* W16      = second ? Whh16 : Wih16;
    #pragma unroll
    for (int u = 0; u < 4; u++)
        sx[tid + u * 256] = __ldg(((const float4*)v) + tid + u * 256);
    __syncthreads();
    const float4* Wr = (const float4*)(W + (size_t)row * D);
    uint4* W16r = (uint4*)(W16 + (size_t)row * D);
    float acc = 0.f;
    #pragma unroll 8
    for (int u = 0; u < 16; u++) {
        int i = lane + u * 32;
        float4 w0 = ldg_ef_f4(Wr + 2 * i, pol);
        float4 w1 = ldg_ef_f4(Wr + 2 * i + 1, pol);
        float4 x0 = sx[2 * i];
        float4 x1 = sx[2 * i + 1];
        uint2 p0 = pack_half4(w0.x, w0.y, w0.z, w0.w);
        uint2 p1 = pack_half4(w1.x, w1.y, w1.z, w1.w);
        uint4 hw; hw.x = p0.x; hw.y = p0.y; hw.z = p1.x; hw.w = p1.y;
        W16r[i] = hw;
        acc += w0.x * x0.x + w0.y * x0.y + w0.z * x0.z + w0.w * x0.w;
        acc += w1.x * x1.x + w1.y * x1.y + w1.z * x1.z + w1.w * x1.w;
    }
    #pragma unroll
    for (int o = 16; o > 0; o >>= 1) acc += __shfl_down_sync(0xffffffffu, acc, o);
    if (lane == 0) outp[row] = acc + bb[row];
}

// GRU combine + LayerNorm (single block, 1024 threads)
__global__ void k_gru_ln(const float* __restrict__ gi, const float* __restrict__ gh,
                         float* __restrict__ state, float* __restrict__ st_out,
                         const float* __restrict__ lng, const float* __restrict__ lnb) {
    __shared__ float red1[32], red2[32];
    int tid = threadIdx.x;
    float h[4];
    float s = 0.f, s2 = 0.f;
    #pragma unroll
    for (int u = 0; u < 4; u++) {
        int e = tid + u * 1024;
        float ir = gi[e], iz = gi[D + e], inn = gi[2 * D + e];
        float hr = gh[e], hz = gh[D + e], hn = gh[2 * D + e];
        float r = sigmoidf(ir + hr);
        float z = sigmoidf(iz + hz);
        float n = tanhf(inn + r * hn);
        float st = state[e];
        float hv = (1.f - z) * n + z * st;
        h[u] = hv; s += hv; s2 += hv * hv;
    }
    #pragma unroll
    for (int o = 16; o > 0; o >>= 1) {
        s  += __shfl_down_sync(0xffffffffu, s, o);
        s2 += __shfl_down_sync(0xffffffffu, s2, o);
    }
    if ((tid & 31) == 0) { red1[tid >> 5] = s; red2[tid >> 5] = s2; }
    __syncthreads();
    if (tid < 32) {
        s = red1[tid]; s2 = red2[tid];
        #pragma unroll
        for (int o = 16; o > 0; o >>= 1) {
            s  += __shfl_down_sync(0xffffffffu, s, o);
            s2 += __shfl_down_sync(0xffffffffu, s2, o);
        }
        if (tid == 0) { red1[0] = s; red2[0] = s2; }
    }
    __syncthreads();
    float mean = red1[0] * (1.f / (float)D);
    float var = red2[0] * (1.f / (float)D) - mean * mean;
    float rstd = rsqrtf(var + 1e-5f);
    #pragma unroll
    for (int u = 0; u < 4; u++) {
        int e = tid + u * 1024;
        float hv = h[u];
        st_out[e] = (hv - mean) * rstd * lng[e] + lnb[e];
        state[e] = hv;
    }
}

__global__ void k_gate_dots(const float* __restrict__ states, const float* __restrict__ cond,
                            const float* __restrict__ gw, float* __restrict__ dots) {
    int warp = threadIdx.x >> 5, lane = threadIdx.x & 31;
    if (warp > 16) return;
    const float* vec = (warp < 16) ? (states + (size_t)warp * D) : cond;
    const float* w   = (warp < 16) ? gw : (gw + D);
    float acc = 0.f;
    for (int i = lane; i < D; i += 32) acc += vec[i] * w[i];
    #pragma unroll
    for (int o = 16; o > 0; o >>= 1) acc += __shfl_down_sync(0xffffffffu, acc, o);
    if (lane == 0) dots[warp] = acc;
}

__global__ void k_summary(const float* __restrict__ states, const float* __restrict__ dots,
                          const float* __restrict__ gate_b, float* __restrict__ out) {
    int j = blockIdx.x * blockDim.x + threadIdx.x;
    float cd = dots[16] + gate_b[0];
    float num = 0.f, den = 0.f;
    #pragma unroll
    for (int t = 0; t < STEPS; t++) {
        float g = sigmoidf(dots[t] + cd);
        num = fmaf(g, states[(size_t)t * D + j], num);
        den += g;
    }
    out[j] = num / fmaxf(den, 1e-6f);
}

// ---------------- host ----------------
static void run_gemv_col(const float* W, const float* x, int K, float* part,
                         const float* add0, const float* add1, const float* bias,
                         int act, float scale, const float* residual, float* out) {
    dim3 grid(D / (256 * 4), SPLITK);
    k_gemv_col_part<<<grid, 256>>>(W, x, K, part);
    k_gemv_col_fin<<<D / 64, 256>>>(part, add0, add1, bias, act, scale, residual, out);
}

static void run_gemv_col_cvt(const float* W, const float* x, float* part, __half* W16,
                             const float* add0, const float* add1, const float* bias,
                             int act, float scale, const float* residual, float* out) {
    dim3 grid(D / (256 * 4), SPLITK);
    k_gemv_col_part_cvt<<<grid, 256>>>(W, x, part, W16);
    k_gemv_col_fin<<<D / 64, 256>>>(part, add0, add1, bias, act, scale, residual, out);
}

extern "C" void kernel_launch(void* const* d_in, const int* in_sizes, int n_in,
                              void* d_out, int out_size) {
    const float* anchor   = (const float*)d_in[0];
    const float* proposal = (const float*)d_in[1];
    const float* context  = (const float*)d_in[2];
    const float* seed_w1  = (const float*)d_in[3];
    const float* seed_b1  = (const float*)d_in[4];
    const float* seed_w2  = (const float*)d_in[5];
    const float* seed_b2  = (const float*)d_in[6];
    const float* cond_w1  = (const float*)d_in[7];
    const float* cond_b1  = (const float*)d_in[8];
    const float* cond_w2  = (const float*)d_in[9];
    const float* cond_b2  = (const float*)d_in[10];
    const float* in_w1    = (const float*)d_in[11];
    const float* in_b1    = (const float*)d_in[12];
    const float* in_w2    = (const float*)d_in[13];
    const float* in_b2    = (const float*)d_in[14];
    const float* step_emb = (const float*)d_in[15];
    const float* w_ih     = (const float*)d_in[16];
    const float* b_ih     = (const float*)d_in[17];
    const float* w_hh     = (const float*)d_in[18];
    const float* b_hh     = (const float*)d_in[19];
    const float* ln_g     = (const float*)d_in[20];
    const float* ln_b     = (const float*)d_in[21];
    const float* gate_w   = (const float*)d_in[22];
    const float* gate_b   = (const float*)d_in[23];

    float* S = nullptr;
    cudaGetSymbolAddress((void**)&S, g_scratch);
    __half* H = nullptr;
    cudaGetSymbolAddress((void**)&H, g_half);

    float* fusion    = S + OFF_FUSION;
    float* hbuf      = S + OFF_HBUF;
    float* condition = S + OFF_COND;
    float* state     = S + OFF_STATE;
    float* cond_c    = S + OFF_CONDC;
    float* emb_c     = S + OFF_EMBC;
    float* h1        = S + OFF_H1;
    float* xbuf      = S + OFF_X;
    float* gi        = S + OFF_GI;
    float* gh        = S + OFF_GH;
    float* part      = S + OFF_PART;
    float* part_e    = S + OFF_PARTE;
    float* dots      = S + OFF_DOTS;

    __half* h_wih   = H + H_WIH;
    __half* h_whh   = H + H_WHH;
    __half* h_inw1s = H + H_INW1S;
    __half* h_inw2  = H + H_INW2;

    float* states  = (float*)d_out;
    float* summary = (float*)d_out + STEPS * D;

    // fusion vector
    k_fusion<<<D / 256, 256>>>(anchor, proposal, context);

    // condition = MLP_cond(fusion)
    run_gemv_col(cond_w1, fusion, FUS, part, nullptr, nullptr, cond_b1, 1, 1.f, nullptr, hbuf);
    run_gemv_col(cond_w2, hbuf, D, part, nullptr, nullptr, cond_b2, 0, 1.f, nullptr, condition);

    // state0 = p + 0.1 * MLP_seed(fusion)
    run_gemv_col(seed_w1, fusion, FUS, part, nullptr, nullptr, seed_b1, 1, 1.f, nullptr, hbuf);
    run_gemv_col(seed_w2, hbuf, D, part, nullptr, nullptr, seed_b2, 0, RES_SCALE, proposal, state);

    // hoisted: condition contribution of in_w1 (rows [0,D)) + in_b1
    run_gemv_col(in_w1, condition, D, part, nullptr, nullptr, in_b1, 0, 1.f, nullptr, cond_c);

    // hoisted: step-embedding contributions of in_w1 (rows [2D,3D)) for all 16 steps
    k_emb_part<<<dim3(D / 256, ESPLIT), 256>>>(in_w1 + (size_t)2 * D * D, step_emb, part_e);
    k_emb_fin<<<(STEPS * D) / 256, 256>>>(part_e, emb_c);

    // ---- step 0 (fp32 weights, emits fp16 copies) ----
    run_gemv_col_cvt(in_w1 + (size_t)D * D, state, part, h_inw1s,
                     cond_c, emb_c, nullptr, 1, 1.f, nullptr, h1);
    run_gemv_col_cvt(in_w2, h1, part, h_inw2,
                     nullptr, nullptr, in_b2, 0, 1.f, nullptr, xbuf);
    k_gemv_row2_cvt<<<(6 * D) / 8, 256>>>(w_ih, xbuf, b_ih, gi,
                                          w_hh, state, b_hh, gh, h_wih, h_whh);
    k_gru_ln<<<1, 1024>>>(gi, gh, state, states, ln_g, ln_b);

    // ---- steps 1..15: gh co-launched with the in_w1s partials (both need only state) ----
    for (int t = 1; t < STEPS; t++) {
        k_step_a<<<GH_BLOCKS + 1024, 256>>>(h_whh, state, b_hh, gh, h_inw1s, part);
        k_gemv_col_fin<<<D / 64, 256>>>(part, cond_c, emb_c + (size_t)t * D,
                                        nullptr, 1, 1.f, nullptr, h1);
        k_gemv_col_part_h<<<dim3(D / (256 * 4), SPLITK), 256>>>(h_inw2, h1, part);
        k_gemv_col_fin<<<D / 64, 256>>>(part, nullptr, nullptr, in_b2, 0, 1.f, nullptr, xbuf);
        k_gemv_row_h<<<(3 * D) / 8, 256>>>(h_wih, xbuf, b_ih, gi);
        k_gru_ln<<<1, 1024>>>(gi, gh, state, states + (size_t)t * D, ln_g, ln_b);
    }

    // gated summary
    k_gate_dots<<<1, 544>>>(states, condition, gate_w, dots);
    k_summary<<<D / 256, 256>>>(states, dots, gate_b, summary);
}

// round 13
// speedup vs baseline: 1.0329x; 1.0329x over previous
#include <cuda_runtime.h>
#include <cuda_fp16.h>
#include <math.h>

#define D 4096
#define HID 4096
#define STEPS 16
#define FUS (5 * D)
#define SPLITK 256
#define ESPLIT 64
#define RES_SCALE 0.1f

// ---------------- scratch ----------------
#define OFF_FUSION   0
#define OFF_HBUF     (OFF_FUSION + FUS)
#define OFF_COND     (OFF_HBUF + HID)
#define OFF_STATE    (OFF_COND + D)
#define OFF_CONDC    (OFF_STATE + D)
#define OFF_EMBC     (OFF_CONDC + D)
#define OFF_H1       (OFF_EMBC + STEPS * D)
#define OFF_X        (OFF_H1 + D)
#define OFF_GI       (OFF_X + D)
#define OFF_GH       (OFF_GI + 3 * D)
#define OFF_PART     (OFF_GH + 3 * D)          // float[SPLITK*D]
#define OFF_PARTE    (OFF_PART + SPLITK * D)
#define OFF_DOTS     (OFF_PARTE + ESPLIT * STEPS * D)
#define SCRATCH_TOTAL (OFF_DOTS + 32)

__device__ float g_scratch[SCRATCH_TOTAL];

// fp16 copies of the recurring weights: [w_ih | w_hh | in_w1_state | in_w2]
#define H_WIH   ((size_t)0)
#define H_WHH   ((size_t)3 * D * D)
#define H_INW1S ((size_t)6 * D * D)
#define H_INW2  ((size_t)7 * D * D)
#define H_TOTAL ((size_t)8 * D * D)
__device__ __half g_half[H_TOTAL];

// ---------------- helpers ----------------
__device__ __forceinline__ float gelu_exact(float v) {
    return 0.5f * v * (1.0f + erff(v * 0.7071067811865476f));
}
__device__ __forceinline__ float sigmoidf(float v) {
    return 1.0f / (1.0f + expf(-v));
}

__device__ __forceinline__ unsigned long long ef_policy() {
    unsigned long long p;
    asm("createpolicy.fractional.L2::evict_first.b64 %0, 1.0;" : "=l"(p));
    return p;
}
__device__ __forceinline__ float4 ldg_ef_f4(const float4* p, unsigned long long pol) {
    float4 v;
    asm volatile("ld.global.L2::cache_hint.v4.f32 {%0,%1,%2,%3}, [%4], %5;"
                 : "=f"(v.x), "=f"(v.y), "=f"(v.z), "=f"(v.w) : "l"(p), "l"(pol));
    return v;
}

__device__ __forceinline__ uint2 pack_half4(float a, float b, float c, float d) {
    __half2 h0 = __floats2half2_rn(a, b);
    __half2 h1 = __floats2half2_rn(c, d);
    uint2 u;
    u.x = *reinterpret_cast<unsigned*>(&h0);
    u.y = *reinterpret_cast<unsigned*>(&h1);
    return u;
}

// ---------------- kernels ----------------

// fusion = [a, p, c, p-a, p*a]
__global__ void k_fusion(const float* __restrict__ a, const float* __restrict__ p,
                         const float* __restrict__ c) {
    int i = blockIdx.x * blockDim.x + threadIdx.x;
    float av = a[i], pv = p[i], cv = c[i];
    float* f = g_scratch + OFF_FUSION;
    f[i] = av; f[D + i] = pv; f[2 * D + i] = cv;
    f[3 * D + i] = pv - av; f[4 * D + i] = pv * av;
}

// fp32 col-major GEMV partial (one-time MLPs). x-slice staged in smem.
__global__ void k_gemv_col_part(const float* __restrict__ W, const float* __restrict__ x,
                                int K, float* __restrict__ part) {
    __shared__ float sx[128];
    unsigned long long pol = ef_policy();
    int tid = threadIdx.x;
    int j4 = (blockIdx.x * blockDim.x + tid) * 4;
    int ks = (int)(((long long)K * blockIdx.y) / gridDim.y);
    int ke = (int)(((long long)K * (blockIdx.y + 1)) / gridDim.y);
    int cnt = ke - ks;
    if (tid < cnt) sx[tid] = __ldg(&x[ks + tid]);
    __syncthreads();
    float4 acc = make_float4(0.f, 0.f, 0.f, 0.f);
    const float4* Wp = (const float4*)(W + (size_t)ks * D + j4);
    #pragma unroll 8
    for (int u = 0; u < cnt; u++) {
        float xv = sx[u];
        float4 w = ldg_ef_f4(Wp, pol);
        Wp += D / 4;
        acc.x = fmaf(xv, w.x, acc.x);
        acc.y = fmaf(xv, w.y, acc.y);
        acc.z = fmaf(xv, w.z, acc.z);
        acc.w = fmaf(xv, w.w, acc.w);
    }
    *(float4*)(part + (size_t)blockIdx.y * D + j4) = acc;
}

// Fused: fp32 GEMV partial + emit fp16 copy of W (step 0, in_w matrices; K == D)
__global__ void k_gemv_col_part_cvt(const float* __restrict__ W, const float* __restrict__ x,
                                    float* __restrict__ part, __half* __restrict__ W16) {
    __shared__ float sx[32];
    unsigned long long pol = ef_policy();
    int tid = threadIdx.x;
    int j4 = (blockIdx.x * blockDim.x + tid) * 4;
    int ks = blockIdx.y * (D / SPLITK);
    if (tid < D / SPLITK) sx[tid] = __ldg(&x[ks + tid]);
    __syncthreads();
    float4 acc = make_float4(0.f, 0.f, 0.f, 0.f);
    #pragma unroll
    for (int u = 0; u < D / SPLITK; u++) {
        int k = ks + u;
        float xv = sx[u];
        float4 w = ldg_ef_f4((const float4*)(W + (size_t)k * D + j4), pol);
        *(uint2*)(W16 + (size_t)k * D + j4) = pack_half4(w.x, w.y, w.z, w.w);
        acc.x = fmaf(xv, w.x, acc.x);
        acc.y = fmaf(xv, w.y, acc.y);
        acc.z = fmaf(xv, w.z, acc.z);
        acc.w = fmaf(xv, w.w, acc.w);
    }
    *(float4*)(part + (size_t)blockIdx.y * D + j4) = acc;
}

// fp16-weight col-major GEMV partial (R9-proven geometry): uint2 loads,
// x-slice (16 values) in registers. grid (4, SPLITK).
__global__ void k_gemv_col_part_h(const __half* __restrict__ W, const float* __restrict__ x,
                                  float* __restrict__ part) {
    int j4 = (blockIdx.x * blockDim.x + threadIdx.x) * 4;
    int ks = blockIdx.y * (D / SPLITK);
    float xs[D / SPLITK];
    #pragma unroll
    for (int u = 0; u < D / SPLITK; u++) xs[u] = __ldg(&x[ks + u]);
    float4 acc = make_float4(0.f, 0.f, 0.f, 0.f);
    #pragma unroll
    for (int u = 0; u < D / SPLITK; u++) {
        uint2 w = *(const uint2*)(W + (size_t)(ks + u) * D + j4);
        float2 f0 = __half22float2(*reinterpret_cast<__half2*>(&w.x));
        float2 f1 = __half22float2(*reinterpret_cast<__half2*>(&w.y));
        acc.x = fmaf(xs[u], f0.x, acc.x);
        acc.y = fmaf(xs[u], f0.y, acc.y);
        acc.z = fmaf(xs[u], f1.x, acc.z);
        acc.w = fmaf(xs[u], f1.y, acc.w);
    }
    *(float4*)(part + (size_t)blockIdx.y * D + j4) = acc;
}

// Finish: sum SPLITK fp32 partials per j, apply epilogue.
__global__ void k_gemv_col_fin(const float* __restrict__ part,
                               const float* __restrict__ add0, const float* __restrict__ add1,
                               const float* __restrict__ bias, int act, float scale,
                               const float* __restrict__ residual, float* __restrict__ out) {
    __shared__ float sh[4][64];
    int jloc = threadIdx.x & 63;
    int tgrp = threadIdx.x >> 6;
    int j = blockIdx.x * 64 + jloc;
    float s = 0.f;
    #pragma unroll
    for (int t = tgrp; t < SPLITK; t += 4) s += part[(size_t)t * D + j];
    sh[tgrp][jloc] = s;
    __syncthreads();
    if (tgrp == 0) {
        s = sh[0][jloc] + sh[1][jloc] + sh[2][jloc] + sh[3][jloc];
        if (add0) s += add0[j];
        if (add1) s += add1[j];
        if (bias) s += bias[j];
        if (act) s = gelu_exact(s);
        if (residual) out[j] = residual[j] + scale * s;
        else out[j] = scale * s;
    }
}

// Step-embedding hoist (one-time, fp32)
__global__ void k_emb_part(const float* __restrict__ We, const float* __restrict__ emb,
                           float* __restrict__ part) {
    __shared__ float se[D / ESPLIT][STEPS];
    unsigned long long pol = ef_policy();
    int tid = threadIdx.x;
    int j = blockIdx.x * blockDim.x + tid;
    int ks = blockIdx.y * (D / ESPLIT);
    for (int i = tid; i < (D / ESPLIT) * STEPS; i += blockDim.x) {
        int kk = i / STEPS, tt = i % STEPS;
        se[kk][tt] = __ldg(&emb[tt * D + ks + kk]);
    }
    __syncthreads();
    float acc[STEPS];
    #pragma unroll
    for (int t = 0; t < STEPS; t++) acc[t] = 0.f;
    #pragma unroll 4
    for (int u = 0; u < D / ESPLIT; u++) {
        float w;
        asm volatile("ld.global.L2::cache_hint.f32 %0, [%1], %2;"
                     : "=f"(w) : "l"(&We[(size_t)(ks + u) * D + j]), "l"(pol));
        #pragma unroll
        for (int t = 0; t < STEPS; t++)
            acc[t] = fmaf(se[u][t], w, acc[t]);
    }
    #pragma unroll
    for (int t = 0; t < STEPS; t++)
        part[((size_t)blockIdx.y * STEPS + t) * D + j] = acc[t];
}

__global__ void k_emb_fin(const float* __restrict__ part, float* __restrict__ out) {
    int idx = blockIdx.x * blockDim.x + threadIdx.x;
    float s = 0.f;
    #pragma unroll
    for (int sp = 0; sp < ESPLIT; sp++) s += part[(size_t)sp * STEPS * D + idx];
    out[idx] = s;
}

// Single-matrix fp16 row GEMV (warp-per-row), vector staged in smem. (R9 inner loop.)
__global__ void k_gemv_row_h(const __half* __restrict__ W, const float* __restrict__ v,
                             const float* __restrict__ bias, float* __restrict__ out) {
    __shared__ float4 sx[D / 4];
    int tid = threadIdx.x;
    int warp = tid >> 5, lane = tid & 31;
    int row = blockIdx.x * 8 + warp;
    #pragma unroll
    for (int u = 0; u < 4; u++)
        sx[tid + u * 256] = __ldg(((const float4*)v) + tid + u * 256);
    __syncthreads();
    const uint4* Wr = (const uint4*)(W + (size_t)row * D);
    float acc = 0.f;
    #pragma unroll
    for (int u = 0; u < 16; u++) {
        int i = lane + u * 32;
        uint4 w = __ldg(Wr + i);
        float4 x0 = sx[2 * i];
        float4 x1 = sx[2 * i + 1];
        float2 f0 = __half22float2(*reinterpret_cast<__half2*>(&w.x));
        float2 f1 = __half22float2(*reinterpret_cast<__half2*>(&w.y));
        float2 f2 = __half22float2(*reinterpret_cast<__half2*>(&w.z));
        float2 f3 = __half22float2(*reinterpret_cast<__half2*>(&w.w));
        acc += f0.x * x0.x + f0.y * x0.y + f1.x * x0.z + f1.y * x0.w;
        acc += f2.x * x1.x + f2.y * x1.y + f3.x * x1.z + f3.y * x1.w;
    }
    #pragma unroll
    for (int o = 16; o > 0; o >>= 1) acc += __shfl_down_sync(0xffffffffu, acc, o);
    if (lane == 0) out[row] = acc + bias[row];
}

// Step 0 variant: fp32 weights for both gate matrices, emits fp16 copies.
__global__ void k_gemv_row2_cvt(const float* __restrict__ Wih, const float* __restrict__ x,
                                const float* __restrict__ bih, float* __restrict__ gi,
                                const float* __restrict__ Whh, const float* __restrict__ st,
                                const float* __restrict__ bhh, float* __restrict__ gh,
                                __half* __restrict__ Wih16, __half* __restrict__ Whh16) {
    __shared__ float4 sx[D / 4];
    unsigned long long pol = ef_policy();
    int tid = threadIdx.x;
    int warp = tid >> 5, lane = tid & 31;
    int grow = blockIdx.x * 8 + warp;
    int second = grow >= 3 * D;
    int row = second ? grow - 3 * D : grow;
    const float* W   = second ? Whh : Wih;
    const float* v   = second ? st  : x;
    const float* bb  = second ? bhh : bih;
    float* outp      = second ? gh  : gi;
    __half* W16      = second ? Whh16 : Wih16;
    #pragma unroll
    for (int u = 0; u < 4; u++)
        sx[tid + u * 256] = __ldg(((const float4*)v) + tid + u * 256);
    __syncthreads();
    const float4* Wr = (const float4*)(W + (size_t)row * D);
    uint4* W16r = (uint4*)(W16 + (size_t)row * D);
    float acc = 0.f;
    #pragma unroll 8
    for (int u = 0; u < 16; u++) {
        int i = lane + u * 32;
        float4 w0 = ldg_ef_f4(Wr + 2 * i, pol);
        float4 w1 = ldg_ef_f4(Wr + 2 * i + 1, pol);
        float4 x0 = sx[2 * i];
        float4 x1 = sx[2 * i + 1];
        uint2 p0 = pack_half4(w0.x, w0.y, w0.z, w0.w);
        uint2 p1 = pack_half4(w1.x, w1.y, w1.z, w1.w);
        uint4 hw; hw.x = p0.x; hw.y = p0.y; hw.z = p1.x; hw.w = p1.y;
        W16r[i] = hw;
        acc += w0.x * x0.x + w0.y * x0.y + w0.z * x0.z + w0.w * x0.w;
        acc += w1.x * x1.x + w1.y * x1.y + w1.z * x1.z + w1.w * x1.w;
    }
    #pragma unroll
    for (int o = 16; o > 0; o >>= 1) acc += __shfl_down_sync(0xffffffffu, acc, o);
    if (lane == 0) outp[row] = acc + bb[row];
}

// GRU combine + LayerNorm (single block, 1024 threads — R9 proven)
__global__ void k_gru_ln(const float* __restrict__ gi, const float* __restrict__ gh,
                         float* __restrict__ state, float* __restrict__ st_out,
                         const float* __restrict__ lng, const float* __restrict__ lnb) {
    __shared__ float red1[32], red2[32];
    int tid = threadIdx.x;
    float h[4];
    float s = 0.f, s2 = 0.f;
    #pragma unroll
    for (int u = 0; u < 4; u++) {
        int e = tid + u * 1024;
        float ir = gi[e], iz = gi[D + e], inn = gi[2 * D + e];
        float hr = gh[e], hz = gh[D + e], hn = gh[2 * D + e];
        float r = sigmoidf(ir + hr);
        float z = sigmoidf(iz + hz);
        float n = tanhf(inn + r * hn);
        float st = state[e];
        float hv = (1.f - z) * n + z * st;
        h[u] = hv; s += hv; s2 += hv * hv;
    }
    #pragma unroll
    for (int o = 16; o > 0; o >>= 1) {
        s  += __shfl_down_sync(0xffffffffu, s, o);
        s2 += __shfl_down_sync(0xffffffffu, s2, o);
    }
    if ((tid & 31) == 0) { red1[tid >> 5] = s; red2[tid >> 5] = s2; }
    __syncthreads();
    if (tid < 32) {
        s = red1[tid]; s2 = red2[tid];
        #pragma unroll
        for (int o = 16; o > 0; o >>= 1) {
            s  += __shfl_down_sync(0xffffffffu, s, o);
            s2 += __shfl_down_sync(0xffffffffu, s2, o);
        }
        if (tid == 0) { red1[0] = s; red2[0] = s2; }
    }
    __syncthreads();
    float mean = red1[0] * (1.f / (float)D);
    float var = red2[0] * (1.f / (float)D) - mean * mean;
    float rstd = rsqrtf(var + 1e-5f);
    #pragma unroll
    for (int u = 0; u < 4; u++) {
        int e = tid + u * 1024;
        float hv = h[u];
        st_out[e] = (hv - mean) * rstd * lng[e] + lnb[e];
        state[e] = hv;
    }
}

__global__ void k_gate_dots(const float* __restrict__ states, const float* __restrict__ cond,
                            const float* __restrict__ gw, float* __restrict__ dots) {
    int warp = threadIdx.x >> 5, lane = threadIdx.x & 31;
    if (warp > 16) return;
    const float* vec = (warp < 16) ? (states + (size_t)warp * D) : cond;
    const float* w   = (warp < 16) ? gw : (gw + D);
    float acc = 0.f;
    for (int i = lane; i < D; i += 32) acc += vec[i] * w[i];
    #pragma unroll
    for (int o = 16; o > 0; o >>= 1) acc += __shfl_down_sync(0xffffffffu, acc, o);
    if (lane == 0) dots[warp] = acc;
}

__global__ void k_summary(const float* __restrict__ states, const float* __restrict__ dots,
                          const float* __restrict__ gate_b, float* __restrict__ out) {
    int j = blockIdx.x * blockDim.x + threadIdx.x;
    float cd = dots[16] + gate_b[0];
    float num = 0.f, den = 0.f;
    #pragma unroll
    for (int t = 0; t < STEPS; t++) {
        float g = sigmoidf(dots[t] + cd);
        num = fmaf(g, states[(size_t)t * D + j], num);
        den += g;
    }
    out[j] = num / fmaxf(den, 1e-6f);
}

// ---------------- host ----------------
static void run_gemv_col(const float* W, const float* x, int K, float* part,
                         const float* add0, const float* add1, const float* bias,
                         int act, float scale, const float* residual, float* out) {
    dim3 grid(D / (256 * 4), SPLITK);
    k_gemv_col_part<<<grid, 256>>>(W, x, K, part);
    k_gemv_col_fin<<<D / 64, 256>>>(part, add0, add1, bias, act, scale, residual, out);
}

static void run_gemv_col_cvt(const float* W, const float* x, float* part, __half* W16,
                             const float* add0, const float* add1, const float* bias,
                             int act, float scale, const float* residual, float* out) {
    dim3 grid(D / (256 * 4), SPLITK);
    k_gemv_col_part_cvt<<<grid, 256>>>(W, x, part, W16);
    k_gemv_col_fin<<<D / 64, 256>>>(part, add0, add1, bias, act, scale, residual, out);
}

static void run_gemv_col_h(const __half* W, const float* x, float* part,
                           const float* add0, const float* add1, const float* bias,
                           int act, float scale, const float* residual, float* out) {
    dim3 grid(D / (256 * 4), SPLITK);
    k_gemv_col_part_h<<<grid, 256>>>(W, x, part);
    k_gemv_col_fin<<<D / 64, 256>>>(part, add0, add1, bias, act, scale, residual, out);
}

extern "C" void kernel_launch(void* const* d_in, const int* in_sizes, int n_in,
                              void* d_out, int out_size) {
    const float* anchor   = (const float*)d_in[0];
    const float* proposal = (const float*)d_in[1];
    const float* context  = (const float*)d_in[2];
    const float* seed_w1  = (const float*)d_in[3];
    const float* seed_b1  = (const float*)d_in[4];
    const float* seed_w2  = (const float*)d_in[5];
    const float* seed_b2  = (const float*)d_in[6];
    const float* cond_w1  = (const float*)d_in[7];
    const float* cond_b1  = (const float*)d_in[8];
    const float* cond_w2  = (const float*)d_in[9];
    const float* cond_b2  = (const float*)d_in[10];
    const float* in_w1    = (const float*)d_in[11];
    const float* in_b1    = (const float*)d_in[12];
    const float* in_w2    = (const float*)d_in[13];
    const float* in_b2    = (const float*)d_in[14];
    const float* step_emb = (const float*)d_in[15];
    const float* w_ih     = (const float*)d_in[16];
    const float* b_ih     = (const float*)d_in[17];
    const float* w_hh     = (const float*)d_in[18];
    const float* b_hh     = (const float*)d_in[19];
    const float* ln_g     = (const float*)d_in[20];
    const float* ln_b     = (const float*)d_in[21];
    const float* gate_w   = (const float*)d_in[22];
    const float* gate_b   = (const float*)d_in[23];

    float* S = nullptr;
    cudaGetSymbolAddress((void**)&S, g_scratch);
    __half* H = nullptr;
    cudaGetSymbolAddress((void**)&H, g_half);

    // one-time stream/event creation (host resources, not device allocations)
    static cudaStream_t s2 = nullptr;
    static cudaEvent_t evA = nullptr, evB = nullptr;
    if (!s2) {
        cudaStreamCreateWithFlags(&s2, cudaStreamNonBlocking);
        cudaEventCreateWithFlags(&evA, cudaEventDisableTiming);
        cudaEventCreateWithFlags(&evB, cudaEventDisableTiming);
    }
    cudaStream_t s0 = 0;

    float* fusion    = S + OFF_FUSION;
    float* hbuf      = S + OFF_HBUF;
    float* condition = S + OFF_COND;
    float* state     = S + OFF_STATE;
    float* cond_c    = S + OFF_CONDC;
    float* emb_c     = S + OFF_EMBC;
    float* h1        = S + OFF_H1;
    float* xbuf      = S + OFF_X;
    float* gi        = S + OFF_GI;
    float* gh        = S + OFF_GH;
    float* part      = S + OFF_PART;
    float* part_e    = S + OFF_PARTE;
    float* dots      = S + OFF_DOTS;

    __half* h_wih   = H + H_WIH;
    __half* h_whh   = H + H_WHH;
    __half* h_inw1s = H + H_INW1S;
    __half* h_inw2  = H + H_INW2;

    float* states  = (float*)d_out;
    float* summary = (float*)d_out + STEPS * D;

    // ---- one-time phase (serial, R9-exact) ----
    k_fusion<<<D / 256, 256>>>(anchor, proposal, context);
    run_gemv_col(cond_w1, fusion, FUS, part, nullptr, nullptr, cond_b1, 1, 1.f, nullptr, hbuf);
    run_gemv_col(cond_w2, hbuf, D, part, nullptr, nullptr, cond_b2, 0, 1.f, nullptr, condition);
    run_gemv_col(seed_w1, fusion, FUS, part, nullptr, nullptr, seed_b1, 1, 1.f, nullptr, hbuf);
    run_gemv_col(seed_w2, hbuf, D, part, nullptr, nullptr, seed_b2, 0, RES_SCALE, proposal, state);
    run_gemv_col(in_w1, condition, D, part, nullptr, nullptr, in_b1, 0, 1.f, nullptr, cond_c);
    k_emb_part<<<dim3(D / 256, ESPLIT), 256>>>(in_w1 + (size_t)2 * D * D, step_emb, part_e);
    k_emb_fin<<<(STEPS * D) / 256, 256>>>(part_e, emb_c);

    // ---- step 0 (serial, fp32 weights, emits fp16 copies; R9-exact) ----
    run_gemv_col_cvt(in_w1 + (size_t)D * D, state, part, h_inw1s,
                     cond_c, emb_c, nullptr, 1, 1.f, nullptr, h1);
    run_gemv_col_cvt(in_w2, h1, part, h_inw2,
                     nullptr, nullptr, in_b2, 0, 1.f, nullptr, xbuf);
    k_gemv_row2_cvt<<<(6 * D) / 8, 256>>>(w_ih, xbuf, b_ih, gi,
                                          w_hh, state, b_hh, gh, h_wih, h_whh);
    k_gru_ln<<<1, 1024>>>(gi, gh, state, states, ln_g, ln_b);

    // ---- steps 1..15: gh on s2, overlapped with h1 -> x -> gi on main ----
    // All kernels and geometries identical to R9; only the schedule forks.
    for (int t = 1; t < STEPS; t++) {
        cudaEventRecord(evA, s0);                 // state is ready (after gru_ln)
        cudaStreamWaitEvent(s2, evA, 0);
        k_gemv_row_h<<<(3 * D) / 8, 256, 0, s2>>>(h_whh, state, b_hh, gh);
        cudaEventRecord(evB, s2);

        run_gemv_col_h(h_inw1s, state, part, cond_c, emb_c + (size_t)t * D,
                       nullptr, 1, 1.f, nullptr, h1);
        run_gemv_col_h(h_inw2, h1, part, nullptr, nullptr, in_b2, 0, 1.f, nullptr, xbuf);
        k_gemv_row_h<<<(3 * D) / 8, 256>>>(h_wih, xbuf, b_ih, gi);

        cudaStreamWaitEvent(s0, evB, 0);          // join gh before GRU
        k_gru_ln<<<1, 1024>>>(gi, gh, state, states + (size_t)t * D, ln_g, ln_b);
    }

    // gated summary
    k_gate_dots<<<1, 544>>>(states, condition, gate_w, dots);
    k_summary<<<D / 256, 256>>>(states, dots, gate_b, summary);
}

// round 14
// speedup vs baseline: 1.0492x; 1.0157x over previous
#include <cuda_runtime.h>
#include <cuda_fp16.h>
#include <math.h>

#define D 4096
#define HID 4096
#define STEPS 16
#define FUS (5 * D)
#define SPLITK 256
#define ESPLIT 64
#define RES_SCALE 0.1f

// ---------------- scratch ----------------
#define OFF_FUSION   0
#define OFF_HBUF     (OFF_FUSION + FUS)
#define OFF_COND     (OFF_HBUF + HID)
#define OFF_STATE    (OFF_COND + D)
#define OFF_CONDC    (OFF_STATE + D)
#define OFF_EMBC     (OFF_CONDC + D)
#define OFF_H1       (OFF_EMBC + STEPS * D)
#define OFF_X        (OFF_H1 + D)
#define OFF_GI       (OFF_X + D)
#define OFF_GH       (OFF_GI + 3 * D)
#define OFF_PART     (OFF_GH + 3 * D)          // float[SPLITK*D]
#define OFF_PARTE    (OFF_PART + SPLITK * D)
#define OFF_DOTS     (OFF_PARTE + ESPLIT * STEPS * D)
#define SCRATCH_TOTAL (OFF_DOTS + 32)

__device__ float g_scratch[SCRATCH_TOTAL];

// fp16 copies: w_ih/w_hh row-major; in_w1_state/in_w2 TRANSPOSED (output-row contiguous)
#define H_WIH   ((size_t)0)
#define H_WHH   ((size_t)3 * D * D)
#define H_INW1S ((size_t)6 * D * D)
#define H_INW2  ((size_t)7 * D * D)
#define H_TOTAL ((size_t)8 * D * D)
__device__ __half g_half[H_TOTAL];

// ---------------- helpers ----------------
__device__ __forceinline__ float gelu_exact(float v) {
    return 0.5f * v * (1.0f + erff(v * 0.7071067811865476f));
}
__device__ __forceinline__ float sigmoidf(float v) {
    return 1.0f / (1.0f + expf(-v));
}

__device__ __forceinline__ unsigned long long ef_policy() {
    unsigned long long p;
    asm("createpolicy.fractional.L2::evict_first.b64 %0, 1.0;" : "=l"(p));
    return p;
}
__device__ __forceinline__ float4 ldg_ef_f4(const float4* p, unsigned long long pol) {
    float4 v;
    asm volatile("ld.global.L2::cache_hint.v4.f32 {%0,%1,%2,%3}, [%4], %5;"
                 : "=f"(v.x), "=f"(v.y), "=f"(v.z), "=f"(v.w) : "l"(p), "l"(pol));
    return v;
}

__device__ __forceinline__ uint2 pack_half4(float a, float b, float c, float d) {
    __half2 h0 = __floats2half2_rn(a, b);
    __half2 h1 = __floats2half2_rn(c, d);
    uint2 u;
    u.x = *reinterpret_cast<unsigned*>(&h0);
    u.y = *reinterpret_cast<unsigned*>(&h1);
    return u;
}

// ---------------- kernels ----------------

// fusion = [a, p, c, p-a, p*a]
__global__ void k_fusion(const float* __restrict__ a, const float* __restrict__ p,
                         const float* __restrict__ c) {
    int i = blockIdx.x * blockDim.x + threadIdx.x;
    float av = a[i], pv = p[i], cv = c[i];
    float* f = g_scratch + OFF_FUSION;
    f[i] = av; f[D + i] = pv; f[2 * D + i] = cv;
    f[3 * D + i] = pv - av; f[4 * D + i] = pv * av;
}

// fp32 col-major GEMV partial (one-time MLPs). x-slice staged in smem.
__global__ void k_gemv_col_part(const float* __restrict__ W, const float* __restrict__ x,
                                int K, float* __restrict__ part) {
    __shared__ float sx[128];
    unsigned long long pol = ef_policy();
    int tid = threadIdx.x;
    int j4 = (blockIdx.x * blockDim.x + tid) * 4;
    int ks = (int)(((long long)K * blockIdx.y) / gridDim.y);
    int ke = (int)(((long long)K * (blockIdx.y + 1)) / gridDim.y);
    int cnt = ke - ks;
    if (tid < cnt) sx[tid] = __ldg(&x[ks + tid]);
    __syncthreads();
    float4 acc = make_float4(0.f, 0.f, 0.f, 0.f);
    const float4* Wp = (const float4*)(W + (size_t)ks * D + j4);
    #pragma unroll 8
    for (int u = 0; u < cnt; u++) {
        float xv = sx[u];
        float4 w = ldg_ef_f4(Wp, pol);
        Wp += D / 4;
        acc.x = fmaf(xv, w.x, acc.x);
        acc.y = fmaf(xv, w.y, acc.y);
        acc.z = fmaf(xv, w.z, acc.z);
        acc.w = fmaf(xv, w.w, acc.w);
    }
    *(float4*)(part + (size_t)blockIdx.y * D + j4) = acc;
}

// Fused step-0: fp32 col GEMV partial + emit TRANSPOSED fp16 copy.
// W is [K=D, D]; W16T[j][k] = W[k][j], output row j contiguous (4096 halfs).
// Transposed-emit correctness validated in R10 (rel_err matched).
__global__ void k_gemv_col_part_cvtT(const float* __restrict__ W, const float* __restrict__ x,
                                     float* __restrict__ part, __half* __restrict__ W16T) {
    __shared__ float sx[16];
    unsigned long long pol = ef_policy();
    int tid = threadIdx.x;
    int j4 = (blockIdx.x * blockDim.x + tid) * 4;
    int ks = blockIdx.y * (D / SPLITK);        // 16 k-rows per block
    if (tid < D / SPLITK) sx[tid] = __ldg(&x[ks + tid]);
    __syncthreads();
    float4 acc = make_float4(0.f, 0.f, 0.f, 0.f);
    __half hb[4][16];                           // [jj][kk]
    #pragma unroll
    for (int u = 0; u < D / SPLITK; u++) {
        float xv = sx[u];
        float4 w = ldg_ef_f4((const float4*)(W + (size_t)(ks + u) * D + j4), pol);
        hb[0][u] = __float2half_rn(w.x);
        hb[1][u] = __float2half_rn(w.y);
        hb[2][u] = __float2half_rn(w.z);
        hb[3][u] = __float2half_rn(w.w);
        acc.x = fmaf(xv, w.x, acc.x);
        acc.y = fmaf(xv, w.y, acc.y);
        acc.z = fmaf(xv, w.z, acc.z);
        acc.w = fmaf(xv, w.w, acc.w);
    }
    #pragma unroll
    for (int jj = 0; jj < 4; jj++) {
        uint4* dst = (uint4*)(W16T + (size_t)(j4 + jj) * D + ks);
        const uint4* src = (const uint4*)&hb[jj][0];
        dst[0] = src[0];
        dst[1] = src[1];
    }
    *(float4*)(part + (size_t)blockIdx.y * D + j4) = acc;
}

// Finish: sum SPLITK fp32 partials per j, apply epilogue.
__global__ void k_gemv_col_fin(const float* __restrict__ part,
                               const float* __restrict__ add0, const float* __restrict__ add1,
                               const float* __restrict__ bias, int act, float scale,
                               const float* __restrict__ residual, float* __restrict__ out) {
    __shared__ float sh[4][64];
    int jloc = threadIdx.x & 63;
    int tgrp = threadIdx.x >> 6;
    int j = blockIdx.x * 64 + jloc;
    float s = 0.f;
    #pragma unroll
    for (int t = tgrp; t < SPLITK; t += 4) s += part[(size_t)t * D + j];
    sh[tgrp][jloc] = s;
    __syncthreads();
    if (tgrp == 0) {
        s = sh[0][jloc] + sh[1][jloc] + sh[2][jloc] + sh[3][jloc];
        if (add0) s += add0[j];
        if (add1) s += add1[j];
        if (bias) s += bias[j];
        if (act) s = gelu_exact(s);
        if (residual) out[j] = residual[j] + scale * s;
        else out[j] = scale * s;
    }
}

// Step-embedding hoist (one-time, fp32)
__global__ void k_emb_part(const float* __restrict__ We, const float* __restrict__ emb,
                           float* __restrict__ part) {
    __shared__ float se[D / ESPLIT][STEPS];
    unsigned long long pol = ef_policy();
    int tid = threadIdx.x;
    int j = blockIdx.x * blockDim.x + tid;
    int ks = blockIdx.y * (D / ESPLIT);
    for (int i = tid; i < (D / ESPLIT) * STEPS; i += blockDim.x) {
        int kk = i / STEPS, tt = i % STEPS;
        se[kk][tt] = __ldg(&emb[tt * D + ks + kk]);
    }
    __syncthreads();
    float acc[STEPS];
    #pragma unroll
    for (int t = 0; t < STEPS; t++) acc[t] = 0.f;
    #pragma unroll 4
    for (int u = 0; u < D / ESPLIT; u++) {
        float w;
        asm volatile("ld.global.L2::cache_hint.f32 %0, [%1], %2;"
                     : "=f"(w) : "l"(&We[(size_t)(ks + u) * D + j]), "l"(pol));
        #pragma unroll
        for (int t = 0; t < STEPS; t++)
            acc[t] = fmaf(se[u][t], w, acc[t]);
    }
    #pragma unroll
    for (int t = 0; t < STEPS; t++)
        part[((size_t)blockIdx.y * STEPS + t) * D + j] = acc[t];
}

__global__ void k_emb_fin(const float* __restrict__ part, float* __restrict__ out) {
    int idx = blockIdx.x * blockDim.x + threadIdx.x;
    float s = 0.f;
    #pragma unroll
    for (int sp = 0; sp < ESPLIT; sp++) s += part[(size_t)sp * STEPS * D + idx];
    out[idx] = s;
}

// Per-step in_w GEMV over transposed fp16 weights, epilogue fused.
// 2 warps per row, 4 rows/block, grid = D/4 = 1024 blocks, 256 threads (high occupancy).
__global__ void k_gemv_rowT2_h(const __half* __restrict__ WT, const float* __restrict__ v,
                               const float* __restrict__ add0, const float* __restrict__ add1,
                               const float* __restrict__ bias, int act,
                               float* __restrict__ out) {
    __shared__ float4 sx[D / 4];       // 16KB staged vector
    __shared__ float sred[8];
    int tid = threadIdx.x;
    int warp = tid >> 5, lane = tid & 31;
    int rloc = warp >> 1;              // 0..3
    int half = warp & 1;               // which half of the row
    int row = blockIdx.x * 4 + rloc;
    #pragma unroll
    for (int u = 0; u < 4; u++)
        sx[tid + u * 256] = __ldg(((const float4*)v) + tid + u * 256);
    __syncthreads();
    const uint4* Wr = (const uint4*)(WT + (size_t)row * D) + half * 256;  // 512 uint4/row
    const float4* sxh = sx + half * 512;
    float acc = 0.f;
    #pragma unroll
    for (int u = 0; u < 8; u++) {
        int i = lane + u * 32;
        uint4 w = __ldg(Wr + i);
        float4 x0 = sxh[2 * i];
        float4 x1 = sxh[2 * i + 1];
        float2 f0 = __half22float2(*reinterpret_cast<__half2*>(&w.x));
        float2 f1 = __half22float2(*reinterpret_cast<__half2*>(&w.y));
        float2 f2 = __half22float2(*reinterpret_cast<__half2*>(&w.z));
        float2 f3 = __half22float2(*reinterpret_cast<__half2*>(&w.w));
        acc += f0.x * x0.x + f0.y * x0.y + f1.x * x0.z + f1.y * x0.w;
        acc += f2.x * x1.x + f2.y * x1.y + f3.x * x1.z + f3.y * x1.w;
    }
    #pragma unroll
    for (int o = 16; o > 0; o >>= 1) acc += __shfl_down_sync(0xffffffffu, acc, o);
    if (lane == 0) sred[warp] = acc;
    __syncthreads();
    if (tid < 4) {
        int r = blockIdx.x * 4 + tid;
        float s = sred[2 * tid] + sred[2 * tid + 1];
        if (add0) s += add0[r];
        if (add1) s += add1[r];
        if (bias) s += bias[r];
        if (act) s = gelu_exact(s);
        out[r] = s;
    }
}

// Fused fp16 row GEMV for both gate matrices (steps 1..15) — R9-proven, 3072 blocks.
__global__ void k_gemv_row2_h(const __half* __restrict__ Wih, const float* __restrict__ x,
                              const float* __restrict__ bih, float* __restrict__ gi,
                              const __half* __restrict__ Whh, const float* __restrict__ st,
                              const float* __restrict__ bhh, float* __restrict__ gh) {
    __shared__ float4 sx[D / 4];
    int tid = threadIdx.x;
    int warp = tid >> 5, lane = tid & 31;
    int grow = blockIdx.x * 8 + warp;
    int second = grow >= 3 * D;
    int row = second ? grow - 3 * D : grow;
    const __half* W  = second ? Whh : Wih;
    const float* v   = second ? st  : x;
    const float* bb  = second ? bhh : bih;
    float* outp      = second ? gh  : gi;
    #pragma unroll
    for (int u = 0; u < 4; u++)
        sx[tid + u * 256] = __ldg(((const float4*)v) + tid + u * 256);
    __syncthreads();
    const uint4* Wr = (const uint4*)(W + (size_t)row * D);
    float acc = 0.f;
    #pragma unroll
    for (int u = 0; u < 16; u++) {
        int i = lane + u * 32;
        uint4 w = __ldg(Wr + i);
        float4 x0 = sx[2 * i];
        float4 x1 = sx[2 * i + 1];
        float2 f0 = __half22float2(*reinterpret_cast<__half2*>(&w.x));
        float2 f1 = __half22float2(*reinterpret_cast<__half2*>(&w.y));
        float2 f2 = __half22float2(*reinterpret_cast<__half2*>(&w.z));
        float2 f3 = __half22float2(*reinterpret_cast<__half2*>(&w.w));
        acc += f0.x * x0.x + f0.y * x0.y + f1.x * x0.z + f1.y * x0.w;
        acc += f2.x * x1.x + f2.y * x1.y + f3.x * x1.z + f3.y * x1.w;
    }
    #pragma unroll
    for (int o = 16; o > 0; o >>= 1) acc += __shfl_down_sync(0xffffffffu, acc, o);
    if (lane == 0) outp[row] = acc + bb[row];
}

// Step 0 variant: fp32 weights for both gate matrices, emits fp16 copies (row-major).
__global__ void k_gemv_row2_cvt(const float* __restrict__ Wih, const float* __restrict__ x,
                                const float* __restrict__ bih, float* __restrict__ gi,
                                const float* __restrict__ Whh, const float* __restrict__ st,
                                const float* __restrict__ bhh, float* __restrict__ gh,
                                __half* __restrict__ Wih16, __half* __restrict__ Whh16) {
    __shared__ float4 sx[D / 4];
    unsigned long long pol = ef_policy();
    int tid = threadIdx.x;
    int warp = tid >> 5, lane = tid & 31;
    int grow = blockIdx.x * 8 + warp;
    int second = grow >= 3 * D;
    int row = second ? grow - 3 * D : grow;
    const float* W   = second ? Whh : Wih;
    const float* v   = second ? st  : x;
    const float* bb  = second ? bhh : bih;
    float* outp      = second ? gh  : gi;
    __half* W16      = second ? Whh16 : Wih16;
    #pragma unroll
    for (int u = 0; u < 4; u++)
        sx[tid + u * 256] = __ldg(((const float4*)v) + tid + u * 256);
    __syncthreads();
    const float4* Wr = (const float4*)(W + (size_t)row * D);
    uint4* W16r = (uint4*)(W16 + (size_t)row * D);
    float acc = 0.f;
    #pragma unroll 8
    for (int u = 0; u < 16; u++) {
        int i = lane + u * 32;
        float4 w0 = ldg_ef_f4(Wr + 2 * i, pol);
        float4 w1 = ldg_ef_f4(Wr + 2 * i + 1, pol);
        float4 x0 = sx[2 * i];
        float4 x1 = sx[2 * i + 1];
        uint2 p0 = pack_half4(w0.x, w0.y, w0.z, w0.w);
        uint2 p1 = pack_half4(w1.x, w1.y, w1.z, w1.w);
        uint4 hw; hw.x = p0.x; hw.y = p0.y; hw.z = p1.x; hw.w = p1.y;
        W16r[i] = hw;
        acc += w0.x * x0.x + w0.y * x0.y + w0.z * x0.z + w0.w * x0.w;
        acc += w1.x * x1.x + w1.y * x1.y + w1.z * x1.z + w1.w * x1.w;
    }
    #pragma unroll
    for (int o = 16; o > 0; o >>= 1) acc += __shfl_down_sync(0xffffffffu, acc, o);
    if (lane == 0) outp[row] = acc + bb[row];
}

// GRU combine + LayerNorm (single block, 1024 threads — R9 proven)
__global__ void k_gru_ln(const float* __restrict__ gi, const float* __restrict__ gh,
                         float* __restrict__ state, float* __restrict__ st_out,
                         const float* __restrict__ lng, const float* __restrict__ lnb) {
    __shared__ float red1[32], red2[32];
    int tid = threadIdx.x;
    float h[4];
    float s = 0.f, s2 = 0.f;
    #pragma unroll
    for (int u = 0; u < 4; u++) {
        int e = tid + u * 1024;
        float ir = gi[e], iz = gi[D + e], inn = gi[2 * D + e];
        float hr = gh[e], hz = gh[D + e], hn = gh[2 * D + e];
        float r = sigmoidf(ir + hr);
        float z = sigmoidf(iz + hz);
        float n = tanhf(inn + r * hn);
        float st = state[e];
        float hv = (1.f - z) * n + z * st;
        h[u] = hv; s += hv; s2 += hv * hv;
    }
    #pragma unroll
    for (int o = 16; o > 0; o >>= 1) {
        s  += __shfl_down_sync(0xffffffffu, s, o);
        s2 += __shfl_down_sync(0xffffffffu, s2, o);
    }
    if ((tid & 31) == 0) { red1[tid >> 5] = s; red2[tid >> 5] = s2; }
    __syncthreads();
    if (tid < 32) {
        s = red1[tid]; s2 = red2[tid];
        #pragma unroll
        for (int o = 16; o > 0; o >>= 1) {
            s  += __shfl_down_sync(0xffffffffu, s, o);
            s2 += __shfl_down_sync(0xffffffffu, s2, o);
        }
        if (tid == 0) { red1[0] = s; red2[0] = s2; }
    }
    __syncthreads();
    float mean = red1[0] * (1.f / (float)D);
    float var = red2[0] * (1.f / (float)D) - mean * mean;
    float rstd = rsqrtf(var + 1e-5f);
    #pragma unroll
    for (int u = 0; u < 4; u++) {
        int e = tid + u * 1024;
        float hv = h[u];
        st_out[e] = (hv - mean) * rstd * lng[e] + lnb[e];
        state[e] = hv;
    }
}

__global__ void k_gate_dots(const float* __restrict__ states, const float* __restrict__ cond,
                            const float* __restrict__ gw, float* __restrict__ dots) {
    int warp = threadIdx.x >> 5, lane = threadIdx.x & 31;
    if (warp > 16) return;
    const float* vec = (warp < 16) ? (states + (size_t)warp * D) : cond;
    const float* w   = (warp < 16) ? gw : (gw + D);
    float acc = 0.f;
    for (int i = lane; i < D; i += 32) acc += vec[i] * w[i];
    #pragma unroll
    for (int o = 16; o > 0; o >>= 1) acc += __shfl_down_sync(0xffffffffu, acc, o);
    if (lane == 0) dots[warp] = acc;
}

__global__ void k_summary(const float* __restrict__ states, const float* __restrict__ dots,
                          const float* __restrict__ gate_b, float* __restrict__ out) {
    int j = blockIdx.x * blockDim.x + threadIdx.x;
    float cd = dots[16] + gate_b[0];
    float num = 0.f, den = 0.f;
    #pragma unroll
    for (int t = 0; t < STEPS; t++) {
        float g = sigmoidf(dots[t] + cd);
        num = fmaf(g, states[(size_t)t * D + j], num);
        den += g;
    }
    out[j] = num / fmaxf(den, 1e-6f);
}

// ---------------- host ----------------
static void run_gemv_col(const float* W, const float* x, int K, float* part,
                         const float* add0, const float* add1, const float* bias,
                         int act, float scale, const float* residual, float* out) {
    dim3 grid(D / (256 * 4), SPLITK);
    k_gemv_col_part<<<grid, 256>>>(W, x, K, part);
    k_gemv_col_fin<<<D / 64, 256>>>(part, add0, add1, bias, act, scale, residual, out);
}

static void run_gemv_col_cvtT(const float* W, const float* x, float* part, __half* W16T,
                              const float* add0, const float* add1, const float* bias,
                              int act, float scale, const float* residual, float* out) {
    dim3 grid(D / (256 * 4), SPLITK);
    k_gemv_col_part_cvtT<<<grid, 256>>>(W, x, part, W16T);
    k_gemv_col_fin<<<D / 64, 256>>>(part, add0, add1, bias, act, scale, residual, out);
}

extern "C" void kernel_launch(void* const* d_in, const int* in_sizes, int n_in,
                              void* d_out, int out_size) {
    const float* anchor   = (const float*)d_in[0];
    const float* proposal = (const float*)d_in[1];
    const float* context  = (const float*)d_in[2];
    const float* seed_w1  = (const float*)d_in[3];
    const float* seed_b1  = (const float*)d_in[4];
    const float* seed_w2  = (const float*)d_in[5];
    const float* seed_b2  = (const float*)d_in[6];
    const float* cond_w1  = (const float*)d_in[7];
    const float* cond_b1  = (const float*)d_in[8];
    const float* cond_w2  = (const float*)d_in[9];
    const float* cond_b2  = (const float*)d_in[10];
    const float* in_w1    = (const float*)d_in[11];
    const float* in_b1    = (const float*)d_in[12];
    const float* in_w2    = (const float*)d_in[13];
    const float* in_b2    = (const float*)d_in[14];
    const float* step_emb = (const float*)d_in[15];
    const float* w_ih     = (const float*)d_in[16];
    const float* b_ih     = (const float*)d_in[17];
    const float* w_hh     = (const float*)d_in[18];
    const float* b_hh     = (const float*)d_in[19];
    const float* ln_g     = (const float*)d_in[20];
    const float* ln_b     = (const float*)d_in[21];
    const float* gate_w   = (const float*)d_in[22];
    const float* gate_b   = (const float*)d_in[23];

    float* S = nullptr;
    cudaGetSymbolAddress((void**)&S, g_scratch);
    __half* H = nullptr;
    cudaGetSymbolAddress((void**)&H, g_half);

    float* fusion    = S + OFF_FUSION;
    float* hbuf      = S + OFF_HBUF;
    float* condition = S + OFF_COND;
    float* state     = S + OFF_STATE;
    float* cond_c    = S + OFF_CONDC;
    float* emb_c     = S + OFF_EMBC;
    float* h1        = S + OFF_H1;
    float* xbuf      = S + OFF_X;
    float* gi        = S + OFF_GI;
    float* gh        = S + OFF_GH;
    float* part      = S + OFF_PART;
    float* part_e    = S + OFF_PARTE;
    float* dots      = S + OFF_DOTS;

    __half* h_wih    = H + H_WIH;
    __half* h_whh    = H + H_WHH;
    __half* h_inw1sT = H + H_INW1S;
    __half* h_inw2T  = H + H_INW2;

    float* states  = (float*)d_out;
    float* summary = (float*)d_out + STEPS * D;

    // ---- one-time phase (serial, R9-exact) ----
    k_fusion<<<D / 256, 256>>>(anchor, proposal, context);
    run_gemv_col(cond_w1, fusion, FUS, part, nullptr, nullptr, cond_b1, 1, 1.f, nullptr, hbuf);
    run_gemv_col(cond_w2, hbuf, D, part, nullptr, nullptr, cond_b2, 0, 1.f, nullptr, condition);
    run_gemv_col(seed_w1, fusion, FUS, part, nullptr, nullptr, seed_b1, 1, 1.f, nullptr, hbuf);
    run_gemv_col(seed_w2, hbuf, D, part, nullptr, nullptr, seed_b2, 0, RES_SCALE, proposal, state);
    run_gemv_col(in_w1, condition, D, part, nullptr, nullptr, in_b1, 0, 1.f, nullptr, cond_c);
    k_emb_part<<<dim3(D / 256, ESPLIT), 256>>>(in_w1 + (size_t)2 * D * D, step_emb, part_e);
    k_emb_fin<<<(STEPS * D) / 256, 256>>>(part_e, emb_c);

    // ---- step 0 (fp32 weights; emits fp16 copies — in_w mats transposed) ----
    run_gemv_col_cvtT(in_w1 + (size_t)D * D, state, part, h_inw1sT,
                      cond_c, emb_c, nullptr, 1, 1.f, nullptr, h1);
    run_gemv_col_cvtT(in_w2, h1, part, h_inw2T,
                      nullptr, nullptr, in_b2, 0, 1.f, nullptr, xbuf);
    k_gemv_row2_cvt<<<(6 * D) / 8, 256>>>(w_ih, xbuf, b_ih, gi,
                                          w_hh, state, b_hh, gh, h_wih, h_whh);
    k_gru_ln<<<1, 1024>>>(gi, gh, state, states, ln_g, ln_b);

    // ---- steps 1..15: 4 launches, row-form throughout, no partial traffic ----
    for (int t = 1; t < STEPS; t++) {
        k_gemv_rowT2_h<<<D / 4, 256>>>(h_inw1sT, state,
                                       cond_c, emb_c + (size_t)t * D, nullptr, 1, h1);
        k_gemv_rowT2_h<<<D / 4, 256>>>(h_inw2T, h1,
                                       nullptr, nullptr, in_b2, 0, xbuf);
        k_gemv_row2_h<<<(6 * D) / 8, 256>>>(h_wih, xbuf, b_ih, gi, h_whh, state, b_hh, gh);
        k_gru_ln<<<1, 1024>>>(gi, gh, state, states + (size_t)t * D, ln_g, ln_b);
    }

    // gated summary
    k_gate_dots<<<1, 544>>>(states, condition, gate_w, dots);
    k_summary<<<D / 256, 256>>>(states, dots, gate_b, summary);
}

// round 15
// speedup vs baseline: 1.1404x; 1.0870x over previous
#include <cuda_runtime.h>
#include <cuda_fp16.h>
#include <math.h>

#define D 4096
#define HID 4096
#define STEPS 16
#define FUS (5 * D)
#define SPLITK 256
#define ESPLIT 64
#define RES_SCALE 0.1f

// ---------------- scratch ----------------
#define OFF_FUSION   0
#define OFF_HBUF     (OFF_FUSION + FUS)
#define OFF_COND     (OFF_HBUF + HID)
#define OFF_STATE    (OFF_COND + D)
#define OFF_CONDC    (OFF_STATE + D)
#define OFF_EMBC     (OFF_CONDC + D)
#define OFF_H1       (OFF_EMBC + STEPS * D)
#define OFF_X        (OFF_H1 + D)
#define OFF_GI       (OFF_X + D)
#define OFF_GH       (OFF_GI + 3 * D)
#define OFF_PART     (OFF_GH + 3 * D)          // float[SPLITK*D]
#define OFF_PARTE    (OFF_PART + SPLITK * D)
#define OFF_DOTS     (OFF_PARTE + ESPLIT * STEPS * D)
#define SCRATCH_TOTAL (OFF_DOTS + 32)

__device__ float g_scratch[SCRATCH_TOTAL];

// fp16 copies of the recurring weights: [w_ih | w_hh | in_w1_state | in_w2]
#define H_WIH   ((size_t)0)
#define H_WHH   ((size_t)3 * D * D)
#define H_INW1S ((size_t)6 * D * D)
#define H_INW2  ((size_t)7 * D * D)
#define H_TOTAL ((size_t)8 * D * D)
__device__ __half g_half[H_TOTAL];

// ---------------- helpers ----------------
__device__ __forceinline__ float gelu_exact(float v) {
    return 0.5f * v * (1.0f + erff(v * 0.7071067811865476f));
}
__device__ __forceinline__ float sigmoidf(float v) {
    return 1.0f / (1.0f + expf(-v));
}

// evict_first via createpolicy + cache_hint (streams that should not thrash L2)
__device__ __forceinline__ unsigned long long ef_policy() {
    unsigned long long p;
    asm("createpolicy.fractional.L2::evict_first.b64 %0, 1.0;" : "=l"(p));
    return p;
}
__device__ __forceinline__ float4 ldg_ef_f4(const float4* p, unsigned long long pol) {
    float4 v;
    asm volatile("ld.global.L2::cache_hint.v4.f32 {%0,%1,%2,%3}, [%4], %5;"
                 : "=f"(v.x), "=f"(v.y), "=f"(v.z), "=f"(v.w) : "l"(p), "l"(pol));
    return v;
}
__device__ __forceinline__ uint4 ldg_ef_u4(const uint4* p, unsigned long long pol) {
    uint4 v;
    asm volatile("ld.global.L2::cache_hint.v4.u32 {%0,%1,%2,%3}, [%4], %5;"
                 : "=r"(v.x), "=r"(v.y), "=r"(v.z), "=r"(v.w) : "l"(p), "l"(pol));
    return v;
}

__device__ __forceinline__ uint2 pack_half4(float a, float b, float c, float d) {
    __half2 h0 = __floats2half2_rn(a, b);
    __half2 h1 = __floats2half2_rn(c, d);
    uint2 u;
    u.x = *reinterpret_cast<unsigned*>(&h0);
    u.y = *reinterpret_cast<unsigned*>(&h1);
    return u;
}

// ---------------- kernels ----------------

// fusion = [a, p, c, p-a, p*a]
__global__ void k_fusion(const float* __restrict__ a, const float* __restrict__ p,
                         const float* __restrict__ c) {
    int i = blockIdx.x * blockDim.x + threadIdx.x;
    float av = a[i], pv = p[i], cv = c[i];
    float* f = g_scratch + OFF_FUSION;
    f[i] = av; f[D + i] = pv; f[2 * D + i] = cv;
    f[3 * D + i] = pv - av; f[4 * D + i] = pv * av;
}

// fp32 col-major GEMV partial. x-slice staged in smem -> hot loop is pure W stream.
__global__ void k_gemv_col_part(const float* __restrict__ W, const float* __restrict__ x,
                                int K, float* __restrict__ part) {
    __shared__ float sx[128];
    unsigned long long pol = ef_policy();
    int tid = threadIdx.x;
    int j4 = (blockIdx.x * blockDim.x + tid) * 4;
    int ks = (int)(((long long)K * blockIdx.y) / gridDim.y);
    int ke = (int)(((long long)K * (blockIdx.y + 1)) / gridDim.y);
    int cnt = ke - ks;                     // 16 (K=4096) or 80 (K=20480)
    if (tid < cnt) sx[tid] = __ldg(&x[ks + tid]);
    __syncthreads();
    float4 acc = make_float4(0.f, 0.f, 0.f, 0.f);
    const float4* Wp = (const float4*)(W + (size_t)ks * D + j4);
    #pragma unroll 8
    for (int u = 0; u < cnt; u++) {
        float xv = sx[u];
        float4 w = ldg_ef_f4(Wp, pol);
        Wp += D / 4;
        acc.x = fmaf(xv, w.x, acc.x);
        acc.y = fmaf(xv, w.y, acc.y);
        acc.z = fmaf(xv, w.z, acc.z);
        acc.w = fmaf(xv, w.w, acc.w);
    }
    *(float4*)(part + (size_t)blockIdx.y * D + j4) = acc;
}

// Fused: fp32 GEMV partial + emit fp16 copy of W (step 0 of the in_w matrices)
__global__ void k_gemv_col_part_cvt(const float* __restrict__ W, const float* __restrict__ x,
                                    int K, float* __restrict__ part, __half* __restrict__ W16) {
    __shared__ float sx[32];
    unsigned long long pol = ef_policy();
    int tid = threadIdx.x;
    int j4 = (blockIdx.x * blockDim.x + tid) * 4;
    int ks = blockIdx.y * (D / SPLITK);    // K == D here
    if (tid < D / SPLITK) sx[tid] = __ldg(&x[ks + tid]);
    __syncthreads();
    float4 acc = make_float4(0.f, 0.f, 0.f, 0.f);
    #pragma unroll
    for (int u = 0; u < D / SPLITK; u++) {
        int k = ks + u;
        float xv = sx[u];
        float4 w = ldg_ef_f4((const float4*)(W + (size_t)k * D + j4), pol);
        *(uint2*)(W16 + (size_t)k * D + j4) = pack_half4(w.x, w.y, w.z, w.w);
        acc.x = fmaf(xv, w.x, acc.x);
        acc.y = fmaf(xv, w.y, acc.y);
        acc.z = fmaf(xv, w.z, acc.z);
        acc.w = fmaf(xv, w.w, acc.w);
    }
    *(float4*)(part + (size_t)blockIdx.y * D + j4) = acc;
}

// fp16-weight col-major GEMV partial (in_w1s/in_w2, K=4096).
// x-slice (16 values) preloaded into REGISTERS: hot loop = pure W LDG + FMA.
__global__ void k_gemv_col_part_h(const __half* __restrict__ W, const float* __restrict__ x,
                                  float* __restrict__ part) {
    int j4 = (blockIdx.x * blockDim.x + threadIdx.x) * 4;
    int ks = blockIdx.y * (D / SPLITK);    // 16 rows per block
    float xs[D / SPLITK];
    #pragma unroll
    for (int u = 0; u < D / SPLITK; u++) xs[u] = __ldg(&x[ks + u]);
    float4 acc = make_float4(0.f, 0.f, 0.f, 0.f);
    #pragma unroll
    for (int u = 0; u < D / SPLITK; u++) {
        uint2 w = *(const uint2*)(W + (size_t)(ks + u) * D + j4);
        float2 f0 = __half22float2(*reinterpret_cast<__half2*>(&w.x));
        float2 f1 = __half22float2(*reinterpret_cast<__half2*>(&w.y));
        acc.x = fmaf(xs[u], f0.x, acc.x);
        acc.y = fmaf(xs[u], f0.y, acc.y);
        acc.z = fmaf(xs[u], f1.x, acc.z);
        acc.w = fmaf(xs[u], f1.y, acc.w);
    }
    *(float4*)(part + (size_t)blockIdx.y * D + j4) = acc;
}

// Finish: sum SPLITK fp32 partials per j, apply epilogue.
__global__ void k_gemv_col_fin(const float* __restrict__ part,
                               const float* __restrict__ add0, const float* __restrict__ add1,
                               const float* __restrict__ bias, int act, float scale,
                               const float* __restrict__ residual, float* __restrict__ out) {
    __shared__ float sh[4][64];
    int jloc = threadIdx.x & 63;
    int tgrp = threadIdx.x >> 6;
    int j = blockIdx.x * 64 + jloc;
    float s = 0.f;
    #pragma unroll
    for (int t = tgrp; t < SPLITK; t += 4) s += part[(size_t)t * D + j];
    sh[tgrp][jloc] = s;
    __syncthreads();
    if (tgrp == 0) {
        s = sh[0][jloc] + sh[1][jloc] + sh[2][jloc] + sh[3][jloc];
        if (add0) s += add0[j];
        if (add1) s += add1[j];
        if (bias) s += bias[j];
        if (act) s = gelu_exact(s);
        if (residual) out[j] = residual[j] + scale * s;
        else out[j] = scale * s;
    }
}

// Step-embedding hoist: emb-slice staged in smem.
__global__ void k_emb_part(const float* __restrict__ We, const float* __restrict__ emb,
                           float* __restrict__ part) {
    __shared__ float se[D / ESPLIT][STEPS];   // 64 x 16 = 4KB
    unsigned long long pol = ef_policy();
    int tid = threadIdx.x;
    int j = blockIdx.x * blockDim.x + tid;
    int ks = blockIdx.y * (D / ESPLIT);
    for (int i = tid; i < (D / ESPLIT) * STEPS; i += blockDim.x) {
        int kk = i / STEPS, tt = i % STEPS;
        se[kk][tt] = __ldg(&emb[tt * D + ks + kk]);
    }
    __syncthreads();
    float acc[STEPS];
    #pragma unroll
    for (int t = 0; t < STEPS; t++) acc[t] = 0.f;
    #pragma unroll 4
    for (int u = 0; u < D / ESPLIT; u++) {
        float w;
        asm volatile("ld.global.L2::cache_hint.f32 %0, [%1], %2;"
                     : "=f"(w) : "l"(&We[(size_t)(ks + u) * D + j]), "l"(pol));
        #pragma unroll
        for (int t = 0; t < STEPS; t++)
            acc[t] = fmaf(se[u][t], w, acc[t]);
    }
    #pragma unroll
    for (int t = 0; t < STEPS; t++)
        part[((size_t)blockIdx.y * STEPS + t) * D + j] = acc[t];
}

__global__ void k_emb_fin(const float* __restrict__ part, float* __restrict__ out) {
    int idx = blockIdx.x * blockDim.x + threadIdx.x;
    float s = 0.f;
    #pragma unroll
    for (int sp = 0; sp < ESPLIT; sp++) s += part[(size_t)sp * STEPS * D + idx];
    out[idx] = s;
}

// Fused fp16 row-major GEMV (steps 1..15). Input vector staged in SMEM;
// hot loop issues ONLY the W global stream.
__global__ void k_gemv_row2_h(const __half* __restrict__ Wih, const float* __restrict__ x,
                              const float* __restrict__ bih, float* __restrict__ gi,
                              const __half* __restrict__ Whh, const float* __restrict__ st,
                              const float* __restrict__ bhh, float* __restrict__ gh) {
    __shared__ float4 sx[D / 4];            // 16KB
    unsigned long long pol = ef_policy();
    int tid = threadIdx.x;
    int warp = tid >> 5, lane = tid & 31;
    int grow = blockIdx.x * 8 + warp;       // 8 rows per block
    int second = grow >= 3 * D;
    int row = second ? grow - 3 * D : grow;
    const __half* W  = second ? Whh : Wih;
    const float* v   = second ? st  : x;
    const float* bb  = second ? bhh : bih;
    float* outp      = second ? gh  : gi;
    // stage vector: 1024 float4 by 256 threads
    #pragma unroll
    for (int u = 0; u < 4; u++)
        sx[tid + u * 256] = __ldg(((const float4*)v) + tid + u * 256);
    __syncthreads();
    const uint4* Wr = (const uint4*)(W + (size_t)row * D);
    float acc = 0.f;
    #pragma unroll
    for (int u = 0; u < 16; u++) {
        int i = lane + u * 32;
        uint4 w = ldg_ef_u4(Wr + i, pol);
        float4 x0 = sx[2 * i];
        float4 x1 = sx[2 * i + 1];
        float2 f0 = __half22float2(*reinterpret_cast<__half2*>(&w.x));
        float2 f1 = __half22float2(*reinterpret_cast<__half2*>(&w.y));
        float2 f2 = __half22float2(*reinterpret_cast<__half2*>(&w.z));
        float2 f3 = __half22float2(*reinterpret_cast<__half2*>(&w.w));
        acc += f0.x * x0.x + f0.y * x0.y + f1.x * x0.z + f1.y * x0.w;
        acc += f2.x * x1.x + f2.y * x1.y + f3.x * x1.z + f3.y * x1.w;
    }
    #pragma unroll
    for (int o = 16; o > 0; o >>= 1) acc += __shfl_down_sync(0xffffffffu, acc, o);
    if (lane == 0) outp[row] = acc + bb[row];
}

// Step 0 variant: fp32 weights, emits fp16 copies. Vector staged in SMEM.
__global__ void k_gemv_row2_cvt(const float* __restrict__ Wih, const float* __restrict__ x,
                                const float* __restrict__ bih, float* __restrict__ gi,
                                const float* __restrict__ Whh, const float* __restrict__ st,
                                const float* __restrict__ bhh, float* __restrict__ gh,
                                __half* __restrict__ Wih16, __half* __restrict__ Whh16) {
    __shared__ float4 sx[D / 4];
    unsigned long long pol = ef_policy();
    int tid = threadIdx.x;
    int warp = tid >> 5, lane = tid & 31;
    int grow = blockIdx.x * 8 + warp;
    int second = grow >= 3 * D;
    int row = second ? grow - 3 * D : grow;
    const float* W   = second ? Whh : Wih;
    const float* v   = second ? st  : x;
    const float* bb  = second ? bhh : bih;
    float* outp      = second ? gh  : gi;
    __half* W16      = second ? Whh16 : Wih16;
    #pragma unroll
    for (int u = 0; u < 4; u++)
        sx[tid + u * 256] = __ldg(((const float4*)v) + tid + u * 256);
    __syncthreads();
    const float4* Wr = (const float4*)(W + (size_t)row * D);
    uint4* W16r = (uint4*)(W16 + (size_t)row * D);
    float acc = 0.f;
    #pragma unroll 8
    for (int u = 0; u < 16; u++) {
        int i = lane + u * 32;
        float4 w0 = ldg_ef_f4(Wr + 2 * i, pol);
        float4 w1 = ldg_ef_f4(Wr + 2 * i + 1, pol);
        float4 x0 = sx[2 * i];
        float4 x1 = sx[2 * i + 1];
        uint2 p0 = pack_half4(w0.x, w0.y, w0.z, w0.w);
        uint2 p1 = pack_half4(w1.x, w1.y, w1.z, w1.w);
        uint4 hw; hw.x = p0.x; hw.y = p0.y; hw.z = p1.x; hw.w = p1.y;
        W16r[i] = hw;
        acc += w0.x * x0.x + w0.y * x0.y + w0.z * x0.z + w0.w * x0.w;
        acc += w1.x * x1.x + w1.y * x1.y + w1.z * x1.z + w1.w * x1.w;
    }
    #pragma unroll
    for (int o = 16; o > 0; o >>= 1) acc += __shfl_down_sync(0xffffffffu, acc, o);
    if (lane == 0) outp[row] = acc + bb[row];
}

// GRU combine + LayerNorm
__global__ void k_gru_ln(const float* __restrict__ gi, const float* __restrict__ gh,
                         float* __restrict__ state, float* __restrict__ st_out,
                         const float* __restrict__ lng, const float* __restrict__ lnb) {
    __shared__ float red1[32], red2[32];
    int tid = threadIdx.x;
    float h[4];
    float s = 0.f, s2 = 0.f;
    #pragma unroll
    for (int u = 0; u < 4; u++) {
        int e = tid + u * 1024;
        float ir = gi[e], iz = gi[D + e], inn = gi[2 * D + e];
        float hr = gh[e], hz = gh[D + e], hn = gh[2 * D + e];
        float r = sigmoidf(ir + hr);
        float z = sigmoidf(iz + hz);
        float n = tanhf(inn + r * hn);
        float st = state[e];
        float hv = (1.f - z) * n + z * st;
        h[u] = hv; s += hv; s2 += hv * hv;
    }
    #pragma unroll
    for (int o = 16; o > 0; o >>= 1) {
        s  += __shfl_down_sync(0xffffffffu, s, o);
        s2 += __shfl_down_sync(0xffffffffu, s2, o);
    }
    if ((tid & 31) == 0) { red1[tid >> 5] = s; red2[tid >> 5] = s2; }
    __syncthreads();
    if (tid < 32) {
        s = red1[tid]; s2 = red2[tid];
        #pragma unroll
        for (int o = 16; o > 0; o >>= 1) {
            s  += __shfl_down_sync(0xffffffffu, s, o);
            s2 += __shfl_down_sync(0xffffffffu, s2, o);
        }
        if (tid == 0) { red1[0] = s; red2[0] = s2; }
    }
    __syncthreads();
    float mean = red1[0] * (1.f / (float)D);
    float var = red2[0] * (1.f / (float)D) - mean * mean;
    float rstd = rsqrtf(var + 1e-5f);
    #pragma unroll
    for (int u = 0; u < 4; u++) {
        int e = tid + u * 1024;
        float hv = h[u];
        st_out[e] = (hv - mean) * rstd * lng[e] + lnb[e];
        state[e] = hv;
    }
}

__global__ void k_gate_dots(const float* __restrict__ states, const float* __restrict__ cond,
                            const float* __restrict__ gw, float* __restrict__ dots) {
    int warp = threadIdx.x >> 5, lane = threadIdx.x & 31;
    if (warp > 16) return;
    const float* vec = (warp < 16) ? (states + (size_t)warp * D) : cond;
    const float* w   = (warp < 16) ? gw : (gw + D);
    float acc = 0.f;
    for (int i = lane; i < D; i += 32) acc += vec[i] * w[i];
    #pragma unroll
    for (int o = 16; o > 0; o >>= 1) acc += __shfl_down_sync(0xffffffffu, acc, o);
    if (lane == 0) dots[warp] = acc;
}

__global__ void k_summary(const float* __restrict__ states, const float* __restrict__ dots,
                          const float* __restrict__ gate_b, float* __restrict__ out) {
    int j = blockIdx.x * blockDim.x + threadIdx.x;
    float cd = dots[16] + gate_b[0];
    float num = 0.f, den = 0.f;
    #pragma unroll
    for (int t = 0; t < STEPS; t++) {
        float g = sigmoidf(dots[t] + cd);
        num = fmaf(g, states[(size_t)t * D + j], num);
        den += g;
    }
    out[j] = num / fmaxf(den, 1e-6f);
}

// ---------------- host ----------------
static void run_gemv_col(const float* W, const float* x, int K, float* part,
                         const float* add0, const float* add1, const float* bias,
                         int act, float scale, const float* residual, float* out) {
    dim3 grid(D / (256 * 4), SPLITK);
    k_gemv_col_part<<<grid, 256>>>(W, x, K, part);
    k_gemv_col_fin<<<D / 64, 256>>>(part, add0, add1, bias, act, scale, residual, out);
}

static void run_gemv_col_cvt(const float* W, const float* x, float* part, __half* W16,
                             const float* add0, const float* add1, const float* bias,
                             int act, float scale, const float* residual, float* out) {
    dim3 grid(D / (256 * 4), SPLITK);
    k_gemv_col_part_cvt<<<grid, 256>>>(W, x, D, part, W16);
    k_gemv_col_fin<<<D / 64, 256>>>(part, add0, add1, bias, act, scale, residual, out);
}

static void run_gemv_col_h(const __half* W, const float* x, float* part,
                           const float* add0, const float* add1, const float* bias,
                           int act, float scale, const float* residual, float* out) {
    dim3 grid(D / (256 * 4), SPLITK);
    k_gemv_col_part_h<<<grid, 256>>>(W, x, part);
    k_gemv_col_fin<<<D / 64, 256>>>(part, add0, add1, bias, act, scale, residual, out);
}

extern "C" void kernel_launch(void* const* d_in, const int* in_sizes, int n_in,
                              void* d_out, int out_size) {
    const float* anchor   = (const float*)d_in[0];
    const float* proposal = (const float*)d_in[1];
    const float* context  = (const float*)d_in[2];
    const float* seed_w1  = (const float*)d_in[3];
    const float* seed_b1  = (const float*)d_in[4];
    const float* seed_w2  = (const float*)d_in[5];
    const float* seed_b2  = (const float*)d_in[6];
    const float* cond_w1  = (const float*)d_in[7];
    const float* cond_b1  = (const float*)d_in[8];
    const float* cond_w2  = (const float*)d_in[9];
    const float* cond_b2  = (const float*)d_in[10];
    const float* in_w1    = (const float*)d_in[11];
    const float* in_b1    = (const float*)d_in[12];
    const float* in_w2    = (const float*)d_in[13];
    const float* in_b2    = (const float*)d_in[14];
    const float* step_emb = (const float*)d_in[15];
    const float* w_ih     = (const float*)d_in[16];
    const float* b_ih     = (const float*)d_in[17];
    const float* w_hh     = (const float*)d_in[18];
    const float* b_hh     = (const float*)d_in[19];
    const float* ln_g     = (const float*)d_in[20];
    const float* ln_b     = (const float*)d_in[21];
    const float* gate_w   = (const float*)d_in[22];
    const float* gate_b   = (const float*)d_in[23];

    float* S = nullptr;
    cudaGetSymbolAddress((void**)&S, g_scratch);
    __half* H = nullptr;
    cudaGetSymbolAddress((void**)&H, g_half);

    float* fusion    = S + OFF_FUSION;
    float* hbuf      = S + OFF_HBUF;
    float* condition = S + OFF_COND;
    float* state     = S + OFF_STATE;
    float* cond_c    = S + OFF_CONDC;
    float* emb_c     = S + OFF_EMBC;
    float* h1        = S + OFF_H1;
    float* xbuf      = S + OFF_X;
    float* gi        = S + OFF_GI;
    float* gh        = S + OFF_GH;
    float* part      = S + OFF_PART;
    float* part_e    = S + OFF_PARTE;
    float* dots      = S + OFF_DOTS;

    __half* h_wih   = H + H_WIH;
    __half* h_whh   = H + H_WHH;
    __half* h_inw1s = H + H_INW1S;
    __half* h_inw2  = H + H_INW2;

    float* states  = (float*)d_out;
    float* summary = (float*)d_out + STEPS * D;

    // fusion vector
    k_fusion<<<D / 256, 256>>>(anchor, proposal, context);

    // condition = MLP_cond(fusion)
    run_gemv_col(cond_w1, fusion, FUS, part, nullptr, nullptr, cond_b1, 1, 1.f, nullptr, hbuf);
    run_gemv_col(cond_w2, hbuf, D, part, nullptr, nullptr, cond_b2, 0, 1.f, nullptr, condition);

    // state0 = p + 0.1 * MLP_seed(fusion)
    run_gemv_col(seed_w1, fusion, FUS, part, nullptr, nullptr, seed_b1, 1, 1.f, nullptr, hbuf);
    run_gemv_col(seed_w2, hbuf, D, part, nullptr, nullptr, seed_b2, 0, RES_SCALE, proposal, state);

    // hoisted: condition contribution of in_w1 (rows [0,D)) + in_b1
    run_gemv_col(in_w1, condition, D, part, nullptr, nullptr, in_b1, 0, 1.f, nullptr, cond_c);

    // hoisted: step-embedding contributions of in_w1 (rows [2D,3D)) for all 16 steps
    k_emb_part<<<dim3(D / 256, ESPLIT), 256>>>(in_w1 + (size_t)2 * D * D, step_emb, part_e);
    k_emb_fin<<<(STEPS * D) / 256, 256>>>(part_e, emb_c);

    // 16 sequential GRU steps (fp16 weights, fp32 accumulate).
    // Step 0 reads fp32 weights and emits the fp16 copies (fused conversion).
    for (int t = 0; t < STEPS; t++) {
        if (t == 0) {
            run_gemv_col_cvt(in_w1 + (size_t)D * D, state, part, h_inw1s,
                             cond_c, emb_c + (size_t)t * D, nullptr, 1, 1.f, nullptr, h1);
            run_gemv_col_cvt(in_w2, h1, part, h_inw2,
                             nullptr, nullptr, in_b2, 0, 1.f, nullptr, xbuf);
            k_gemv_row2_cvt<<<(6 * D) / 8, 256>>>(w_ih, xbuf, b_ih, gi,
                                                  w_hh, state, b_hh, gh, h_wih, h_whh);
        } else {
            run_gemv_col_h(h_inw1s, state, part, cond_c, emb_c + (size_t)t * D,
                           nullptr, 1, 1.f, nullptr, h1);
            run_gemv_col_h(h_inw2, h1, part, nullptr, nullptr, in_b2, 0, 1.f, nullptr, xbuf);
            k_gemv_row2_h<<<(6 * D) / 8, 256>>>(h_wih, xbuf, b_ih, gi, h_whh, state, b_hh, gh);
        }
        k_gru_ln<<<1, 1024>>>(gi, gh, state, states + (size_t)t * D, ln_g, ln_b);
    }

    // gated summary
    k_gate_dots<<<1, 544>>>(states, condition, gate_w, dots);
    k_summary<<<D / 256, 256>>>(states, dots, gate_b, summary);
}

// round 16
// speedup vs baseline: 1.1754x; 1.0307x over previous
#include <cuda_runtime.h>
#include <cuda_fp16.h>
#include <math.h>

#define D 4096
#define HID 4096
#define STEPS 16
#define FUS (5 * D)
#define SPLITK 256
#define ESPLIT 64
#define RES_SCALE 0.1f

// ---------------- scratch ----------------
#define OFF_FUSION   0
#define OFF_HBUF     (OFF_FUSION + FUS)
#define OFF_COND     (OFF_HBUF + HID)
#define OFF_HST      (OFF_COND + D)             // (STEPS+1)*D state history; hst[0]=state0
#define OFF_CONDC    (OFF_HST + (STEPS + 1) * D)
#define OFF_EMBC     (OFF_CONDC + D)
#define OFF_H1       (OFF_EMBC + STEPS * D)
#define OFF_X        (OFF_H1 + D)
#define OFF_GI       (OFF_X + D)
#define OFF_GH       (OFF_GI + 3 * D)
#define OFF_PART     (OFF_GH + 3 * D)           // float[SPLITK*D]
#define OFF_PARTE    (OFF_PART + SPLITK * D)
#define OFF_DOTS     (OFF_PARTE + ESPLIT * STEPS * D)
#define SCRATCH_TOTAL (OFF_DOTS + 32)

__device__ float g_scratch[SCRATCH_TOTAL];

// fp16 copies of the recurring weights: [w_ih | w_hh | in_w1_state | in_w2]
#define H_WIH   ((size_t)0)
#define H_WHH   ((size_t)3 * D * D)
#define H_INW1S ((size_t)6 * D * D)
#define H_INW2  ((size_t)7 * D * D)
#define H_TOTAL ((size_t)8 * D * D)
__device__ __half g_half[H_TOTAL];

// ---------------- helpers ----------------
__device__ __forceinline__ float gelu_exact(float v) {
    return 0.5f * v * (1.0f + erff(v * 0.7071067811865476f));
}
__device__ __forceinline__ float sigmoidf(float v) {
    return 1.0f / (1.0f + expf(-v));
}

__device__ __forceinline__ unsigned long long ef_policy() {
    unsigned long long p;
    asm("createpolicy.fractional.L2::evict_first.b64 %0, 1.0;" : "=l"(p));
    return p;
}
__device__ __forceinline__ float4 ldg_ef_f4(const float4* p, unsigned long long pol) {
    float4 v;
    asm volatile("ld.global.L2::cache_hint.v4.f32 {%0,%1,%2,%3}, [%4], %5;"
                 : "=f"(v.x), "=f"(v.y), "=f"(v.z), "=f"(v.w) : "l"(p), "l"(pol));
    return v;
}
__device__ __forceinline__ uint4 ldg_ef_u4(const uint4* p, unsigned long long pol) {
    uint4 v;
    asm volatile("ld.global.L2::cache_hint.v4.u32 {%0,%1,%2,%3}, [%4], %5;"
                 : "=r"(v.x), "=r"(v.y), "=r"(v.z), "=r"(v.w) : "l"(p), "l"(pol));
    return v;
}

__device__ __forceinline__ uint2 pack_half4(float a, float b, float c, float d) {
    __half2 h0 = __floats2half2_rn(a, b);
    __half2 h1 = __floats2half2_rn(c, d);
    uint2 u;
    u.x = *reinterpret_cast<unsigned*>(&h0);
    u.y = *reinterpret_cast<unsigned*>(&h1);
    return u;
}

// ---------------- kernels ----------------

// fusion = [a, p, c, p-a, p*a]
__global__ void k_fusion(const float* __restrict__ a, const float* __restrict__ p,
                         const float* __restrict__ c) {
    int i = blockIdx.x * blockDim.x + threadIdx.x;
    float av = a[i], pv = p[i], cv = c[i];
    float* f = g_scratch + OFF_FUSION;
    f[i] = av; f[D + i] = pv; f[2 * D + i] = cv;
    f[3 * D + i] = pv - av; f[4 * D + i] = pv * av;
}

// fp32 col-major GEMV partial. x-slice staged in smem -> hot loop is pure W stream.
__global__ void k_gemv_col_part(const float* __restrict__ W, const float* __restrict__ x,
                                int K, float* __restrict__ part) {
    __shared__ float sx[128];
    unsigned long long pol = ef_policy();
    int tid = threadIdx.x;
    int j4 = (blockIdx.x * blockDim.x + tid) * 4;
    int ks = (int)(((long long)K * blockIdx.y) / gridDim.y);
    int ke = (int)(((long long)K * (blockIdx.y + 1)) / gridDim.y);
    int cnt = ke - ks;
    if (tid < cnt) sx[tid] = __ldg(&x[ks + tid]);
    __syncthreads();
    float4 acc = make_float4(0.f, 0.f, 0.f, 0.f);
    const float4* Wp = (const float4*)(W + (size_t)ks * D + j4);
    #pragma unroll 8
    for (int u = 0; u < cnt; u++) {
        float xv = sx[u];
        float4 w = ldg_ef_f4(Wp, pol);
        Wp += D / 4;
        acc.x = fmaf(xv, w.x, acc.x);
        acc.y = fmaf(xv, w.y, acc.y);
        acc.z = fmaf(xv, w.z, acc.z);
        acc.w = fmaf(xv, w.w, acc.w);
    }
    *(float4*)(part + (size_t)blockIdx.y * D + j4) = acc;
}

// Fused: fp32 GEMV partial + emit fp16 copy of W (step 0 of the in_w matrices)
__global__ void k_gemv_col_part_cvt(const float* __restrict__ W, const float* __restrict__ x,
                                    int K, float* __restrict__ part, __half* __restrict__ W16) {
    __shared__ float sx[32];
    unsigned long long pol = ef_policy();
    int tid = threadIdx.x;
    int j4 = (blockIdx.x * blockDim.x + tid) * 4;
    int ks = blockIdx.y * (D / SPLITK);
    if (tid < D / SPLITK) sx[tid] = __ldg(&x[ks + tid]);
    __syncthreads();
    float4 acc = make_float4(0.f, 0.f, 0.f, 0.f);
    #pragma unroll
    for (int u = 0; u < D / SPLITK; u++) {
        int k = ks + u;
        float xv = sx[u];
        float4 w = ldg_ef_f4((const float4*)(W + (size_t)k * D + j4), pol);
        *(uint2*)(W16 + (size_t)k * D + j4) = pack_half4(w.x, w.y, w.z, w.w);
        acc.x = fmaf(xv, w.x, acc.x);
        acc.y = fmaf(xv, w.y, acc.y);
        acc.z = fmaf(xv, w.z, acc.z);
        acc.w = fmaf(xv, w.w, acc.w);
    }
    *(float4*)(part + (size_t)blockIdx.y * D + j4) = acc;
}

// fp16-weight col-major GEMV partial (in_w1s/in_w2, K=4096).
// x-slice (16 values) preloaded into REGISTERS: hot loop = pure W LDG + FMA.
__global__ void k_gemv_col_part_h(const __half* __restrict__ W, const float* __restrict__ x,
                                  float* __restrict__ part) {
    int j4 = (blockIdx.x * blockDim.x + threadIdx.x) * 4;
    int ks = blockIdx.y * (D / SPLITK);
    float xs[D / SPLITK];
    #pragma unroll
    for (int u = 0; u < D / SPLITK; u++) xs[u] = __ldg(&x[ks + u]);
    float4 acc = make_float4(0.f, 0.f, 0.f, 0.f);
    #pragma unroll
    for (int u = 0; u < D / SPLITK; u++) {
        uint2 w = *(const uint2*)(W + (size_t)(ks + u) * D + j4);
        float2 f0 = __half22float2(*reinterpret_cast<__half2*>(&w.x));
        float2 f1 = __half22float2(*reinterpret_cast<__half2*>(&w.y));
        acc.x = fmaf(xs[u], f0.x, acc.x);
        acc.y = fmaf(xs[u], f0.y, acc.y);
        acc.z = fmaf(xs[u], f1.x, acc.z);
        acc.w = fmaf(xs[u], f1.y, acc.w);
    }
    *(float4*)(part + (size_t)blockIdx.y * D + j4) = acc;
}

// Finish: sum SPLITK fp32 partials per j, apply epilogue.
__global__ void k_gemv_col_fin(const float* __restrict__ part,
                               const float* __restrict__ add0, const float* __restrict__ add1,
                               const float* __restrict__ bias, int act, float scale,
                               const float* __restrict__ residual, float* __restrict__ out) {
    __shared__ float sh[4][64];
    int jloc = threadIdx.x & 63;
    int tgrp = threadIdx.x >> 6;
    int j = blockIdx.x * 64 + jloc;
    float s = 0.f;
    #pragma unroll
    for (int t = tgrp; t < SPLITK; t += 4) s += part[(size_t)t * D + j];
    sh[tgrp][jloc] = s;
    __syncthreads();
    if (tgrp == 0) {
        s = sh[0][jloc] + sh[1][jloc] + sh[2][jloc] + sh[3][jloc];
        if (add0) s += add0[j];
        if (add1) s += add1[j];
        if (bias) s += bias[j];
        if (act) s = gelu_exact(s);
        if (residual) out[j] = residual[j] + scale * s;
        else out[j] = scale * s;
    }
}

// Step-embedding hoist: emb-slice staged in smem.
__global__ void k_emb_part(const float* __restrict__ We, const float* __restrict__ emb,
                           float* __restrict__ part) {
    __shared__ float se[D / ESPLIT][STEPS];
    unsigned long long pol = ef_policy();
    int tid = threadIdx.x;
    int j = blockIdx.x * blockDim.x + tid;
    int ks = blockIdx.y * (D / ESPLIT);
    for (int i = tid; i < (D / ESPLIT) * STEPS; i += blockDim.x) {
        int kk = i / STEPS, tt = i % STEPS;
        se[kk][tt] = __ldg(&emb[tt * D + ks + kk]);
    }
    __syncthreads();
    float acc[STEPS];
    #pragma unroll
    for (int t = 0; t < STEPS; t++) acc[t] = 0.f;
    #pragma unroll 4
    for (int u = 0; u < D / ESPLIT; u++) {
        float w;
        asm volatile("ld.global.L2::cache_hint.f32 %0, [%1], %2;"
                     : "=f"(w) : "l"(&We[(size_t)(ks + u) * D + j]), "l"(pol));
        #pragma unroll
        for (int t = 0; t < STEPS; t++)
            acc[t] = fmaf(se[u][t], w, acc[t]);
    }
    #pragma unroll
    for (int t = 0; t < STEPS; t++)
        part[((size_t)blockIdx.y * STEPS + t) * D + j] = acc[t];
}

__global__ void k_emb_fin(const float* __restrict__ part, float* __restrict__ out) {
    int idx = blockIdx.x * blockDim.x + threadIdx.x;
    float s = 0.f;
    #pragma unroll
    for (int sp = 0; sp < ESPLIT; sp++) s += part[(size_t)sp * STEPS * D + idx];
    out[idx] = s;
}

// Fused fp16 row-major GEMV (steps 1..15). Input vector staged in SMEM.
__global__ void k_gemv_row2_h(const __half* __restrict__ Wih, const float* __restrict__ x,
                              const float* __restrict__ bih, float* __restrict__ gi,
                              const __half* __restrict__ Whh, const float* __restrict__ st,
                              const float* __restrict__ bhh, float* __restrict__ gh) {
    __shared__ float4 sx[D / 4];
    unsigned long long pol = ef_policy();
    int tid = threadIdx.x;
    int warp = tid >> 5, lane = tid & 31;
    int grow = blockIdx.x * 8 + warp;
    int second = grow >= 3 * D;
    int row = second ? grow - 3 * D : grow;
    const __half* W  = second ? Whh : Wih;
    const float* v   = second ? st  : x;
    const float* bb  = second ? bhh : bih;
    float* outp      = second ? gh  : gi;
    #pragma unroll
    for (int u = 0; u < 4; u++)
        sx[tid + u * 256] = __ldg(((const float4*)v) + tid + u * 256);
    __syncthreads();
    const uint4* Wr = (const uint4*)(W + (size_t)row * D);
    float acc = 0.f;
    #pragma unroll
    for (int u = 0; u < 16; u++) {
        int i = lane + u * 32;
        uint4 w = ldg_ef_u4(Wr + i, pol);
        float4 x0 = sx[2 * i];
        float4 x1 = sx[2 * i + 1];
        float2 f0 = __half22float2(*reinterpret_cast<__half2*>(&w.x));
        float2 f1 = __half22float2(*reinterpret_cast<__half2*>(&w.y));
        float2 f2 = __half22float2(*reinterpret_cast<__half2*>(&w.z));
        float2 f3 = __half22float2(*reinterpret_cast<__half2*>(&w.w));
        acc += f0.x * x0.x + f0.y * x0.y + f1.x * x0.z + f1.y * x0.w;
        acc += f2.x * x1.x + f2.y * x1.y + f3.x * x1.z + f3.y * x1.w;
    }
    #pragma unroll
    for (int o = 16; o > 0; o >>= 1) acc += __shfl_down_sync(0xffffffffu, acc, o);
    if (lane == 0) outp[row] = acc + bb[row];
}

// Step 0 variant: fp32 weights, emits fp16 copies. Vector staged in SMEM.
__global__ void k_gemv_row2_cvt(const float* __restrict__ Wih, const float* __restrict__ x,
                                const float* __restrict__ bih, float* __restrict__ gi,
                                const float* __restrict__ Whh, const float* __restrict__ st,
                                const float* __restrict__ bhh, float* __restrict__ gh,
                                __half* __restrict__ Wih16, __half* __restrict__ Whh16) {
    __shared__ float4 sx[D / 4];
    unsigned long long pol = ef_policy();
    int tid = threadIdx.x;
    int warp = tid >> 5, lane = tid & 31;
    int grow = blockIdx.x * 8 + warp;
    int second = grow >= 3 * D;
    int row = second ? grow - 3 * D : grow;
    const float* W   = second ? Whh : Wih;
    const float* v   = second ? st  : x;
    const float* bb  = second ? bhh : bih;
    float* outp      = second ? gh  : gi;
    __half* W16      = second ? Whh16 : Wih16;
    #pragma unroll
    for (int u = 0; u < 4; u++)
        sx[tid + u * 256] = __ldg(((const float4*)v) + tid + u * 256);
    __syncthreads();
    const float4* Wr = (const float4*)(W + (size_t)row * D);
    uint4* W16r = (uint4*)(W16 + (size_t)row * D);
    float acc = 0.f;
    #pragma unroll 8
    for (int u = 0; u < 16; u++) {
        int i = lane + u * 32;
        float4 w0 = ldg_ef_f4(Wr + 2 * i, pol);
        float4 w1 = ldg_ef_f4(Wr + 2 * i + 1, pol);
        float4 x0 = sx[2 * i];
        float4 x1 = sx[2 * i + 1];
        uint2 p0 = pack_half4(w0.x, w0.y, w0.z, w0.w);
        uint2 p1 = pack_half4(w1.x, w1.y, w1.z, w1.w);
        uint4 hw; hw.x = p0.x; hw.y = p0.y; hw.z = p1.x; hw.w = p1.y;
        W16r[i] = hw;
        acc += w0.x * x0.x + w0.y * x0.y + w0.z * x0.z + w0.w * x0.w;
        acc += w1.x * x1.x + w1.y * x1.y + w1.z * x1.z + w1.w * x1.w;
    }
    #pragma unroll
    for (int o = 16; o > 0; o >>= 1) acc += __shfl_down_sync(0xffffffffu, acc, o);
    if (lane == 0) outp[row] = acc + bb[row];
}

// Elementwise GRU combine (NO LayerNorm): h = (1-z)*n + z*prev.
// 16 blocks x 256 threads — fully parallel, no single-block serialization.
__global__ void k_gru(const float* __restrict__ gi, const float* __restrict__ gh,
                      const float* __restrict__ prev, float* __restrict__ hout) {
    int e = blockIdx.x * blockDim.x + threadIdx.x;
    float ir = gi[e], iz = gi[D + e], inn = gi[2 * D + e];
    float hr = gh[e], hz = gh[D + e], hn = gh[2 * D + e];
    float r = sigmoidf(ir + hr);
    float z = sigmoidf(iz + hz);
    float n = tanhf(inn + r * hn);
    hout[e] = (1.f - z) * n + z * prev[e];
}

// Deferred LayerNorm over all STEPS states at once: block t normalizes hst[t+1] -> states[t].
__global__ void k_ln_all(const float* __restrict__ hst,
                         const float* __restrict__ lng, const float* __restrict__ lnb,
                         float* __restrict__ states) {
    __shared__ float red1[8], red2[8];
    int t = blockIdx.x;
    const float* h = hst + (size_t)(t + 1) * D;
    float* out = states + (size_t)t * D;
    int tid = threadIdx.x;             // 256 threads, 16 elems each
    float v[16];
    float s = 0.f, s2 = 0.f;
    #pragma unroll
    for (int u = 0; u < 16; u++) {
        float hv = h[tid + u * 256];
        v[u] = hv; s += hv; s2 += hv * hv;
    }
    #pragma unroll
    for (int o = 16; o > 0; o >>= 1) {
        s  += __shfl_down_sync(0xffffffffu, s, o);
        s2 += __shfl_down_sync(0xffffffffu, s2, o);
    }
    if ((tid & 31) == 0) { red1[tid >> 5] = s; red2[tid >> 5] = s2; }
    __syncthreads();
    if (tid == 0) {
        float a = 0.f, b = 0.f;
        #pragma unroll
        for (int g = 0; g < 8; g++) { a += red1[g]; b += red2[g]; }
        red1[0] = a; red2[0] = b;
    }
    __syncthreads();
    float mean = red1[0] * (1.f / (float)D);
    float var = red2[0] * (1.f / (float)D) - mean * mean;
    float rstd = rsqrtf(var + 1e-5f);
    #pragma unroll
    for (int u = 0; u < 16; u++) {
        int e = tid + u * 256;
        out[e] = (v[u] - mean) * rstd * lng[e] + lnb[e];
    }
}

__global__ void k_gate_dots(const float* __restrict__ states, const float* __restrict__ cond,
                            const float* __restrict__ gw, float* __restrict__ dots) {
    int warp = threadIdx.x >> 5, lane = threadIdx.x & 31;
    if (warp > 16) return;
    const float* vec = (warp < 16) ? (states + (size_t)warp * D) : cond;
    const float* w   = (warp < 16) ? gw : (gw + D);
    float acc = 0.f;
    for (int i = lane; i < D; i += 32) acc += vec[i] * w[i];
    #pragma unroll
    for (int o = 16; o > 0; o >>= 1) acc += __shfl_down_sync(0xffffffffu, acc, o);
    if (lane == 0) dots[warp] = acc;
}

__global__ void k_summary(const float* __restrict__ states, const float* __restrict__ dots,
                          const float* __restrict__ gate_b, float* __restrict__ out) {
    int j = blockIdx.x * blockDim.x + threadIdx.x;
    float cd = dots[16] + gate_b[0];
    float num = 0.f, den = 0.f;
    #pragma unroll
    for (int t = 0; t < STEPS; t++) {
        float g = sigmoidf(dots[t] + cd);
        num = fmaf(g, states[(size_t)t * D + j], num);
        den += g;
    }
    out[j] = num / fmaxf(den, 1e-6f);
}

// ---------------- host ----------------
static void run_gemv_col(const float* W, const float* x, int K, float* part,
                         const float* add0, const float* add1, const float* bias,
                         int act, float scale, const float* residual, float* out) {
    dim3 grid(D / (256 * 4), SPLITK);
    k_gemv_col_part<<<grid, 256>>>(W, x, K, part);
    k_gemv_col_fin<<<D / 64, 256>>>(part, add0, add1, bias, act, scale, residual, out);
}

static void run_gemv_col_cvt(const float* W, const float* x, float* part, __half* W16,
                             const float* add0, const float* add1, const float* bias,
                             int act, float scale, const float* residual, float* out) {
    dim3 grid(D / (256 * 4), SPLITK);
    k_gemv_col_part_cvt<<<grid, 256>>>(W, x, D, part, W16);
    k_gemv_col_fin<<<D / 64, 256>>>(part, add0, add1, bias, act, scale, residual, out);
}

static void run_gemv_col_h(const __half* W, const float* x, float* part,
                           const float* add0, const float* add1, const float* bias,
                           int act, float scale, const float* residual, float* out) {
    dim3 grid(D / (256 * 4), SPLITK);
    k_gemv_col_part_h<<<grid, 256>>>(W, x, part);
    k_gemv_col_fin<<<D / 64, 256>>>(part, add0, add1, bias, act, scale, residual, out);
}

extern "C" void kernel_launch(void* const* d_in, const int* in_sizes, int n_in,
                              void* d_out, int out_size) {
    const float* anchor   = (const float*)d_in[0];
    const float* proposal = (const float*)d_in[1];
    const float* context  = (const float*)d_in[2];
    const float* seed_w1  = (const float*)d_in[3];
    const float* seed_b1  = (const float*)d_in[4];
    const float* seed_w2  = (const float*)d_in[5];
    const float* seed_b2  = (const float*)d_in[6];
    const float* cond_w1  = (const float*)d_in[7];
    const float* cond_b1  = (const float*)d_in[8];
    const float* cond_w2  = (const float*)d_in[9];
    const float* cond_b2  = (const float*)d_in[10];
    const float* in_w1    = (const float*)d_in[11];
    const float* in_b1    = (const float*)d_in[12];
    const float* in_w2    = (const float*)d_in[13];
    const float* in_b2    = (const float*)d_in[14];
    const float* step_emb = (const float*)d_in[15];
    const float* w_ih     = (const float*)d_in[16];
    const float* b_ih     = (const float*)d_in[17];
    const float* w_hh     = (const float*)d_in[18];
    const float* b_hh     = (const float*)d_in[19];
    const float* ln_g     = (const float*)d_in[20];
    const float* ln_b     = (const float*)d_in[21];
    const float* gate_w   = (const float*)d_in[22];
    const float* gate_b   = (const float*)d_in[23];

    float* S = nullptr;
    cudaGetSymbolAddress((void**)&S, g_scratch);
    __half* H = nullptr;
    cudaGetSymbolAddress((void**)&H, g_half);

    float* fusion    = S + OFF_FUSION;
    float* hbuf      = S + OFF_HBUF;
    float* condition = S + OFF_COND;
    float* hst       = S + OFF_HST;       // hst[0]=state0, hst[t+1]=h after step t
    float* cond_c    = S + OFF_CONDC;
    float* emb_c     = S + OFF_EMBC;
    float* h1        = S + OFF_H1;
    float* xbuf      = S + OFF_X;
    float* gi        = S + OFF_GI;
    float* gh        = S + OFF_GH;
    float* part      = S + OFF_PART;
    float* part_e    = S + OFF_PARTE;
    float* dots      = S + OFF_DOTS;

    __half* h_wih   = H + H_WIH;
    __half* h_whh   = H + H_WHH;
    __half* h_inw1s = H + H_INW1S;
    __half* h_inw2  = H + H_INW2;

    float* states  = (float*)d_out;
    float* summary = (float*)d_out + STEPS * D;

    // fusion vector
    k_fusion<<<D / 256, 256>>>(anchor, proposal, context);

    // condition = MLP_cond(fusion)
    run_gemv_col(cond_w1, fusion, FUS, part, nullptr, nullptr, cond_b1, 1, 1.f, nullptr, hbuf);
    run_gemv_col(cond_w2, hbuf, D, part, nullptr, nullptr, cond_b2, 0, 1.f, nullptr, condition);

    // state0 = p + 0.1 * MLP_seed(fusion)  -> hst[0]
    run_gemv_col(seed_w1, fusion, FUS, part, nullptr, nullptr, seed_b1, 1, 1.f, nullptr, hbuf);
    run_gemv_col(seed_w2, hbuf, D, part, nullptr, nullptr, seed_b2, 0, RES_SCALE, proposal, hst);

    // hoisted: condition contribution of in_w1 (rows [0,D)) + in_b1
    run_gemv_col(in_w1, condition, D, part, nullptr, nullptr, in_b1, 0, 1.f, nullptr, cond_c);

    // hoisted: step-embedding contributions of in_w1 (rows [2D,3D)) for all 16 steps
    k_emb_part<<<dim3(D / 256, ESPLIT), 256>>>(in_w1 + (size_t)2 * D * D, step_emb, part_e);
    k_emb_fin<<<(STEPS * D) / 256, 256>>>(part_e, emb_c);

    // 16 sequential GRU steps. Carry is the RAW h (LN deferred off the critical path).
    for (int t = 0; t < STEPS; t++) {
        const float* st_in = hst + (size_t)t * D;
        float* st_out      = hst + (size_t)(t + 1) * D;
        if (t == 0) {
            run_gemv_col_cvt(in_w1 + (size_t)D * D, st_in, part, h_inw1s,
                             cond_c, emb_c + (size_t)t * D, nullptr, 1, 1.f, nullptr, h1);
            run_gemv_col_cvt(in_w2, h1, part, h_inw2,
                             nullptr, nullptr, in_b2, 0, 1.f, nullptr, xbuf);
            k_gemv_row2_cvt<<<(6 * D) / 8, 256>>>(w_ih, xbuf, b_ih, gi,
                                                  w_hh, st_in, b_hh, gh, h_wih, h_whh);
        } else {
            run_gemv_col_h(h_inw1s, st_in, part, cond_c, emb_c + (size_t)t * D,
                           nullptr, 1, 1.f, nullptr, h1);
            run_gemv_col_h(h_inw2, h1, part, nullptr, nullptr, in_b2, 0, 1.f, nullptr, xbuf);
            k_gemv_row2_h<<<(6 * D) / 8, 256>>>(h_wih, xbuf, b_ih, gi, h_whh, st_in, b_hh, gh);
        }
        k_gru<<<D / 256, 256>>>(gi, gh, st_in, st_out);   // elementwise, 16 blocks
    }

    // deferred LayerNorm for all 16 steps (fully parallel, off critical path)
    k_ln_all<<<STEPS, 256>>>(hst, ln_g, ln_b, states);

    // gated summary
    k_gate_dots<<<1, 544>>>(states, condition, gate_w, dots);
    k_summary<<<D / 256, 256>>>(states, dots, gate_b, summary);
}